// round 1
// baseline (speedup 1.0000x reference)
#include <cuda_runtime.h>
#include <cuda_bf16.h>
#include <math.h>

#define BATCH 64
#define NNODE 512
#define NEDGE 4
#define CIN   64
#define CHID  128
#define COUT  16

// ---------------- scratch (device globals; no allocations allowed) ----------------
__device__ float g_deg[BATCH * NNODE * NEDGE];              // rsqrt(clip(deg,1))
__device__ float g_A[(size_t)BATCH * NNODE * NNODE];        // collapsed normalized adjacency (64 MB)
__device__ float g_hin[(size_t)BATCH * NNODE * CHID];       // GEMM input  (h = x@W)
__device__ float g_hout[(size_t)BATCH * NNODE * CHID];      // GEMM output (silu(mask*(A@h+b)))

// ---------------- K1: degree (with self-loops), store rsqrt(max(sum,1)) ----------------
__global__ void deg_kernel(const float* __restrict__ adj) {
    int bi = blockIdx.x;                 // b*NNODE + i
    int i  = bi & (NNODE - 1);
    const float4* row = (const float4*)(adj + (size_t)bi * (NNODE * NEDGE));
    float4 s = make_float4(0.f, 0.f, 0.f, 0.f);
    for (int j = threadIdx.x; j < NNODE; j += blockDim.x) {
        float4 v = row[j];
        if (j == i) v = make_float4(1.f, 1.f, 1.f, 1.f);   // self loop
        s.x += v.x; s.y += v.y; s.z += v.z; s.w += v.w;
    }
    // warp reduce
    for (int o = 16; o > 0; o >>= 1) {
        s.x += __shfl_down_sync(0xffffffffu, s.x, o);
        s.y += __shfl_down_sync(0xffffffffu, s.y, o);
        s.z += __shfl_down_sync(0xffffffffu, s.z, o);
        s.w += __shfl_down_sync(0xffffffffu, s.w, o);
    }
    __shared__ float4 sh[4];
    int lane = threadIdx.x & 31, w = threadIdx.x >> 5;
    if (lane == 0) sh[w] = s;
    __syncthreads();
    if (threadIdx.x == 0) {
        float4 t = sh[0];
        t.x += sh[1].x + sh[2].x + sh[3].x;
        t.y += sh[1].y + sh[2].y + sh[3].y;
        t.z += sh[1].z + sh[2].z + sh[3].z;
        t.w += sh[1].w + sh[2].w + sh[3].w;
        float4 r;
        r.x = rsqrtf(fmaxf(t.x, 1.f));
        r.y = rsqrtf(fmaxf(t.y, 1.f));
        r.z = rsqrtf(fmaxf(t.z, 1.f));
        r.w = rsqrtf(fmaxf(t.w, 1.f));
        ((float4*)g_deg)[bi] = r;
    }
}

// ---------------- K2: A[b,i,j] = sum_f deg[b,i,f]*adjSL[b,i,j,f]*deg[b,j,f] ----------------
__global__ void buildA_kernel(const float* __restrict__ adj) {
    size_t t = (size_t)blockIdx.x * blockDim.x + threadIdx.x;   // over B*N*N
    int j = (int)(t & (NNODE - 1));
    int i = (int)((t >> 9) & (NNODE - 1));
    int b = (int)(t >> 18);
    float4 a = ((const float4*)adj)[t];
    if (i == j) a = make_float4(1.f, 1.f, 1.f, 1.f);
    float4 di = ((const float4*)g_deg)[b * NNODE + i];
    float4 dj = ((const float4*)g_deg)[b * NNODE + j];
    g_A[t] = a.x * di.x * dj.x + a.y * di.y * dj.y + a.z * di.z * dj.z + a.w * di.w * dj.w;
}

// ---------------- K3: Y(R x 128) = X(R x K) @ W(K x 128), no bias ----------------
__global__ void lin_kernel(const float* __restrict__ X, const float* __restrict__ W,
                           float* __restrict__ Y, int K) {
    int r = blockIdx.x;
    int c = threadIdx.x;                  // 128 threads = output cols
    __shared__ float xs[CHID];
    if (c < K) xs[c] = X[(size_t)r * K + c];
    __syncthreads();
    float acc = 0.f;
    for (int k = 0; k < K; k++) acc = fmaf(xs[k], W[k * CHID + c], acc);
    Y[(size_t)r * CHID + c] = acc;
}

// ---------------- K4: per-batch GEMM out = silu(mask * (A @ Hin + bias)) ----------------
#define BM 128
#define BN 128
#define BKK 8

__global__ __launch_bounds__(256)
void gcn_gemm_kernel(const float* __restrict__ Agl, const float* __restrict__ Hin,
                     const float* __restrict__ bias, const int* __restrict__ mask,
                     float* __restrict__ Hout) {
    int b  = blockIdx.x >> 2;
    int mt = blockIdx.x & 3;
    const float* Ab = Agl + (size_t)b * NNODE * NNODE + (size_t)mt * BM * NNODE;
    const float* Hb = Hin + (size_t)b * NNODE * CHID;
    float*       Ob = Hout + (size_t)b * NNODE * CHID + (size_t)mt * BM * CHID;
    const int*   mb = mask + b * NNODE + mt * BM;

    __shared__ float As[BKK][BM];
    __shared__ float Bs[BKK][BN];

    int tid = threadIdx.x;
    int tx = tid & 15;     // col group (8 cols each)
    int ty = tid >> 4;     // row group (8 rows each)

    float acc[8][8];
#pragma unroll
    for (int u = 0; u < 8; u++)
#pragma unroll
        for (int v = 0; v < 8; v++) acc[u][v] = 0.f;

    int arow = tid >> 1;            // 0..127
    int acol = (tid & 1) * 4;       // 0 or 4
    int brow = tid >> 5;            // 0..7
    int bcol = (tid & 31) * 4;      // 0..124

    for (int k0 = 0; k0 < NNODE; k0 += BKK) {
        float4 a = *(const float4*)(Ab + (size_t)arow * NNODE + k0 + acol);
        As[acol + 0][arow] = a.x;
        As[acol + 1][arow] = a.y;
        As[acol + 2][arow] = a.z;
        As[acol + 3][arow] = a.w;
        *(float4*)(&Bs[brow][bcol]) = *(const float4*)(Hb + (size_t)(k0 + brow) * CHID + bcol);
        __syncthreads();
#pragma unroll
        for (int kk = 0; kk < BKK; kk++) {
            float ra[8], rb[8];
            *(float4*)(ra)     = *(const float4*)(&As[kk][ty * 8]);
            *(float4*)(ra + 4) = *(const float4*)(&As[kk][ty * 8 + 4]);
            *(float4*)(rb)     = *(const float4*)(&Bs[kk][tx * 8]);
            *(float4*)(rb + 4) = *(const float4*)(&Bs[kk][tx * 8 + 4]);
#pragma unroll
            for (int u = 0; u < 8; u++)
#pragma unroll
                for (int v = 0; v < 8; v++)
                    acc[u][v] = fmaf(ra[u], rb[v], acc[u][v]);
        }
        __syncthreads();
    }

#pragma unroll
    for (int u = 0; u < 8; u++) {
        int row = ty * 8 + u;
        float mf = (float)mb[row];
#pragma unroll
        for (int v = 0; v < 8; v++) {
            int col = tx * 8 + v;
            float z = (acc[u][v] + bias[col]) * mf;
            float sgm = 1.f / (1.f + __expf(-z));
            Ob[(size_t)row * CHID + col] = z * sgm;
        }
    }
}

// ---------------- K5: pool over nodes + 2-layer MLP head ----------------
__global__ void head_kernel(const float* __restrict__ hfinal,
                            const float* __restrict__ Wl1, const float* __restrict__ bl1,
                            const float* __restrict__ Wl2, const float* __restrict__ bl2,
                            float* __restrict__ out) {
    int b = blockIdx.x;
    int c = threadIdx.x;       // 128 threads
    float s = 0.f;
    const float* base = hfinal + (size_t)b * NNODE * CHID;
    for (int i = 0; i < NNODE; i++) s += base[(size_t)i * CHID + c];
    __shared__ float g[CHID], g1[CHID];
    g[c] = s * (1.0f / NNODE);
    __syncthreads();
    float acc = bl1[c];
    for (int k = 0; k < CHID; k++) acc = fmaf(g[k], Wl1[k * CHID + c], acc);
    g1[c] = acc / (1.f + __expf(-acc));
    __syncthreads();
    if (c < COUT) {
        float acc2 = bl2[c];
        for (int k = 0; k < CHID; k++) acc2 = fmaf(g1[k], Wl2[k * COUT + c], acc2);
        out[b * COUT + c] = acc2;
    }
}

// ---------------- launch ----------------
extern "C" void kernel_launch(void* const* d_in, const int* in_sizes, int n_in,
                              void* d_out, int out_size) {
    const float* x    = (const float*)d_in[0];
    const float* adj  = (const float*)d_in[1];
    const int*   mask = (const int*)  d_in[2];
    const float* W0   = (const float*)d_in[3];
    const float* b0   = (const float*)d_in[4];
    const float* W1   = (const float*)d_in[5];
    const float* b1   = (const float*)d_in[6];
    const float* Wl1  = (const float*)d_in[7];
    const float* bl1  = (const float*)d_in[8];
    const float* Wl2  = (const float*)d_in[9];
    const float* bl2  = (const float*)d_in[10];
    float* out = (float*)d_out;

    float *dA, *dHin, *dHout;
    cudaGetSymbolAddress((void**)&dA,    g_A);
    cudaGetSymbolAddress((void**)&dHin,  g_hin);
    cudaGetSymbolAddress((void**)&dHout, g_hout);

    // 1) degrees
    deg_kernel<<<BATCH * NNODE, 128>>>(adj);
    // 2) collapsed normalized adjacency
    buildA_kernel<<<(BATCH * NNODE * NNODE) / 256, 256>>>(adj);
    // 3) h0 = x @ W0
    lin_kernel<<<BATCH * NNODE, CHID>>>(x, W0, dHin, CIN);
    // 4) layer 1: hout = silu(mask * (A @ h0 + b0))
    gcn_gemm_kernel<<<BATCH * 4, 256>>>(dA, dHin, b0, mask, dHout);
    // 5) h2 = h1 @ W1
    lin_kernel<<<BATCH * NNODE, CHID>>>(dHout, W1, dHin, CHID);
    // 6) layer 2
    gcn_gemm_kernel<<<BATCH * 4, 256>>>(dA, dHin, b1, mask, dHout);
    // 7) mean pool + MLP head
    head_kernel<<<BATCH, CHID>>>(dHout, Wl1, bl1, Wl2, bl2, out);
}

// round 2
// speedup vs baseline: 1.0063x; 1.0063x over previous
#include <cuda_runtime.h>
#include <cuda_bf16.h>
#include <math.h>

#define BATCH 64
#define NNODE 512
#define NEDGE 4
#define CIN   64
#define CHID  128
#define COUT  16

// ---------------- scratch (device globals; no allocations allowed) ----------------
__device__ float g_deg[BATCH * NNODE * NEDGE];              // rsqrt(clip(deg,1))
__device__ float g_A[(size_t)BATCH * NNODE * NNODE];        // collapsed normalized adjacency (64 MB)
__device__ float g_hin[(size_t)BATCH * NNODE * CHID];       // GEMM input  (h = x@W)
__device__ float g_hout[(size_t)BATCH * NNODE * CHID];      // GEMM output (silu(mask*(A@h+b)))

// ---------------- K1: degree (with self-loops), store rsqrt(max(sum,1)) ----------------
__global__ void deg_kernel(const float* __restrict__ adj) {
    int bi = blockIdx.x;                 // b*NNODE + i
    int i  = bi & (NNODE - 1);
    const float4* row = (const float4*)(adj + (size_t)bi * (NNODE * NEDGE));
    float4 s = make_float4(0.f, 0.f, 0.f, 0.f);
    for (int j = threadIdx.x; j < NNODE; j += blockDim.x) {
        float4 v = row[j];
        if (j == i) v = make_float4(1.f, 1.f, 1.f, 1.f);   // self loop
        s.x += v.x; s.y += v.y; s.z += v.z; s.w += v.w;
    }
    // warp reduce
    for (int o = 16; o > 0; o >>= 1) {
        s.x += __shfl_down_sync(0xffffffffu, s.x, o);
        s.y += __shfl_down_sync(0xffffffffu, s.y, o);
        s.z += __shfl_down_sync(0xffffffffu, s.z, o);
        s.w += __shfl_down_sync(0xffffffffu, s.w, o);
    }
    __shared__ float4 sh[4];
    int lane = threadIdx.x & 31, w = threadIdx.x >> 5;
    if (lane == 0) sh[w] = s;
    __syncthreads();
    if (threadIdx.x == 0) {
        float4 t = sh[0];
        t.x += sh[1].x + sh[2].x + sh[3].x;
        t.y += sh[1].y + sh[2].y + sh[3].y;
        t.z += sh[1].z + sh[2].z + sh[3].z;
        t.w += sh[1].w + sh[2].w + sh[3].w;
        float4 r;
        r.x = rsqrtf(fmaxf(t.x, 1.f));
        r.y = rsqrtf(fmaxf(t.y, 1.f));
        r.z = rsqrtf(fmaxf(t.z, 1.f));
        r.w = rsqrtf(fmaxf(t.w, 1.f));
        ((float4*)g_deg)[bi] = r;
    }
}

// ---------------- K2: A[b,i,j] = sum_f deg[b,i,f]*adjSL[b,i,j,f]*deg[b,j,f] ----------------
__global__ void buildA_kernel(const float* __restrict__ adj) {
    size_t t = (size_t)blockIdx.x * blockDim.x + threadIdx.x;   // over B*N*N
    int j = (int)(t & (NNODE - 1));
    int i = (int)((t >> 9) & (NNODE - 1));
    int b = (int)(t >> 18);
    float4 a = ((const float4*)adj)[t];
    if (i == j) a = make_float4(1.f, 1.f, 1.f, 1.f);
    float4 di = ((const float4*)g_deg)[b * NNODE + i];
    float4 dj = ((const float4*)g_deg)[b * NNODE + j];
    g_A[t] = a.x * di.x * dj.x + a.y * di.y * dj.y + a.z * di.z * dj.z + a.w * di.w * dj.w;
}

// ---------------- K3: Y(R x 128) = X(R x K) @ W(K x 128), no bias ----------------
__global__ void lin_kernel(const float* __restrict__ X, const float* __restrict__ W,
                           float* __restrict__ Y, int K) {
    int r = blockIdx.x;
    int c = threadIdx.x;                  // 128 threads = output cols
    __shared__ float xs[CHID];
    if (c < K) xs[c] = X[(size_t)r * K + c];
    __syncthreads();
    float acc = 0.f;
    for (int k = 0; k < K; k++) acc = fmaf(xs[k], W[k * CHID + c], acc);
    Y[(size_t)r * CHID + c] = acc;
}

// ---------------- K4: per-batch GEMM out = silu(mask * (A @ Hin + bias)) ----------------
#define BM 128
#define BN 128
#define BKK 8

__global__ __launch_bounds__(256)
void gcn_gemm_kernel(const float* __restrict__ Agl, const float* __restrict__ Hin,
                     const float* __restrict__ bias, const int* __restrict__ mask,
                     float* __restrict__ Hout) {
    int b  = blockIdx.x >> 2;
    int mt = blockIdx.x & 3;
    const float* Ab = Agl + (size_t)b * NNODE * NNODE + (size_t)mt * BM * NNODE;
    const float* Hb = Hin + (size_t)b * NNODE * CHID;
    float*       Ob = Hout + (size_t)b * NNODE * CHID + (size_t)mt * BM * CHID;
    const int*   mb = mask + b * NNODE + mt * BM;

    __shared__ float As[BKK][BM];
    __shared__ float Bs[BKK][BN];

    int tid = threadIdx.x;
    int tx = tid & 15;     // col group (8 cols each)
    int ty = tid >> 4;     // row group (8 rows each)

    float acc[8][8];
#pragma unroll
    for (int u = 0; u < 8; u++)
#pragma unroll
        for (int v = 0; v < 8; v++) acc[u][v] = 0.f;

    int arow = tid >> 1;            // 0..127
    int acol = (tid & 1) * 4;       // 0 or 4
    int brow = tid >> 5;            // 0..7
    int bcol = (tid & 31) * 4;      // 0..124

    for (int k0 = 0; k0 < NNODE; k0 += BKK) {
        float4 a = *(const float4*)(Ab + (size_t)arow * NNODE + k0 + acol);
        As[acol + 0][arow] = a.x;
        As[acol + 1][arow] = a.y;
        As[acol + 2][arow] = a.z;
        As[acol + 3][arow] = a.w;
        *(float4*)(&Bs[brow][bcol]) = *(const float4*)(Hb + (size_t)(k0 + brow) * CHID + bcol);
        __syncthreads();
#pragma unroll
        for (int kk = 0; kk < BKK; kk++) {
            float ra[8], rb[8];
            *(float4*)(ra)     = *(const float4*)(&As[kk][ty * 8]);
            *(float4*)(ra + 4) = *(const float4*)(&As[kk][ty * 8 + 4]);
            *(float4*)(rb)     = *(const float4*)(&Bs[kk][tx * 8]);
            *(float4*)(rb + 4) = *(const float4*)(&Bs[kk][tx * 8 + 4]);
#pragma unroll
            for (int u = 0; u < 8; u++)
#pragma unroll
                for (int v = 0; v < 8; v++)
                    acc[u][v] = fmaf(ra[u], rb[v], acc[u][v]);
        }
        __syncthreads();
    }

#pragma unroll
    for (int u = 0; u < 8; u++) {
        int row = ty * 8 + u;
        float mf = (float)mb[row];
#pragma unroll
        for (int v = 0; v < 8; v++) {
            int col = tx * 8 + v;
            float z = (acc[u][v] + bias[col]) * mf;
            float sgm = 1.f / (1.f + __expf(-z));
            Ob[(size_t)row * CHID + col] = z * sgm;
        }
    }
}

// ---------------- K5: pool over nodes + 2-layer MLP head ----------------
__global__ void head_kernel(const float* __restrict__ hfinal,
                            const float* __restrict__ Wl1, const float* __restrict__ bl1,
                            const float* __restrict__ Wl2, const float* __restrict__ bl2,
                            float* __restrict__ out) {
    int b = blockIdx.x;
    int c = threadIdx.x;       // 128 threads
    float s = 0.f;
    const float* base = hfinal + (size_t)b * NNODE * CHID;
    for (int i = 0; i < NNODE; i++) s += base[(size_t)i * CHID + c];
    __shared__ float g[CHID], g1[CHID];
    g[c] = s * (1.0f / NNODE);
    __syncthreads();
    float acc = bl1[c];
    for (int k = 0; k < CHID; k++) acc = fmaf(g[k], Wl1[k * CHID + c], acc);
    g1[c] = acc / (1.f + __expf(-acc));
    __syncthreads();
    if (c < COUT) {
        float acc2 = bl2[c];
        for (int k = 0; k < CHID; k++) acc2 = fmaf(g1[k], Wl2[k * COUT + c], acc2);
        out[b * COUT + c] = acc2;
    }
}

// ---------------- launch ----------------
extern "C" void kernel_launch(void* const* d_in, const int* in_sizes, int n_in,
                              void* d_out, int out_size) {
    const float* x    = (const float*)d_in[0];
    const float* adj  = (const float*)d_in[1];
    const int*   mask = (const int*)  d_in[2];
    const float* W0   = (const float*)d_in[3];
    const float* b0   = (const float*)d_in[4];
    const float* W1   = (const float*)d_in[5];
    const float* b1   = (const float*)d_in[6];
    const float* Wl1  = (const float*)d_in[7];
    const float* bl1  = (const float*)d_in[8];
    const float* Wl2  = (const float*)d_in[9];
    const float* bl2  = (const float*)d_in[10];
    float* out = (float*)d_out;

    float *dA, *dHin, *dHout;
    cudaGetSymbolAddress((void**)&dA,    g_A);
    cudaGetSymbolAddress((void**)&dHin,  g_hin);
    cudaGetSymbolAddress((void**)&dHout, g_hout);

    // 1) degrees
    deg_kernel<<<BATCH * NNODE, 128>>>(adj);
    // 2) collapsed normalized adjacency
    buildA_kernel<<<(BATCH * NNODE * NNODE) / 256, 256>>>(adj);
    // 3) h0 = x @ W0
    lin_kernel<<<BATCH * NNODE, CHID>>>(x, W0, dHin, CIN);
    // 4) layer 1: hout = silu(mask * (A @ h0 + b0))
    gcn_gemm_kernel<<<BATCH * 4, 256>>>(dA, dHin, b0, mask, dHout);
    // 5) h2 = h1 @ W1
    lin_kernel<<<BATCH * NNODE, CHID>>>(dHout, W1, dHin, CHID);
    // 6) layer 2
    gcn_gemm_kernel<<<BATCH * 4, 256>>>(dA, dHin, b1, mask, dHout);
    // 7) mean pool + MLP head
    head_kernel<<<BATCH, CHID>>>(dHout, Wl1, bl1, Wl2, bl2, out);
}

// round 4
// speedup vs baseline: 1.6993x; 1.6886x over previous
#include <cuda_runtime.h>
#include <cuda_bf16.h>
#include <cstdint>
#include <math.h>

#define BATCH 64
#define NNODE 512
#define NEDGE 4
#define CIN   64
#define CHID  128
#define COUT  16

// ---- mma.sync GEMM tiling ----
#define KC 64                               // K per pipeline chunk
#define NCHUNK (NNODE / KC)                 // 8
#define ASTR 144                            // A smem row stride bytes (64 bf16 + 8 pad)
#define HSTR 272                            // H smem row stride bytes (128 bf16 + 8 pad)
#define OFF_AHI 0
#define OFF_ALO (128 * ASTR)                // 18432
#define OFF_HHI (2 * 128 * ASTR)            // 36864
#define OFF_HLO (2 * 128 * ASTR + 64 * HSTR)
#define STAGEB  (2 * 128 * ASTR + 2 * 64 * HSTR)   // 71680
#define SMEM_DYN (2 * STAGEB)                       // 143360

// ---------------- device scratch ----------------
__device__ float          g_deg [BATCH * NNODE * NEDGE];
__device__ __nv_bfloat16  g_Ahi [(size_t)BATCH * NNODE * NNODE];   // 32MB
__device__ __nv_bfloat16  g_Alo [(size_t)BATCH * NNODE * NNODE];   // 32MB
__device__ __nv_bfloat16  g_Hhi [(size_t)BATCH * NNODE * CHID];    // 8MB  [b][k][n]
__device__ __nv_bfloat16  g_Hlo [(size_t)BATCH * NNODE * CHID];    // 8MB
__device__ float          g_hout[(size_t)BATCH * NNODE * CHID];    // 16MB

// ---------------- PTX helpers ----------------
__device__ __forceinline__ uint32_t smem_u32(const void* p) {
    uint32_t a;
    asm("{ .reg .u64 t; cvta.to.shared.u64 t, %1; cvt.u32.u64 %0, t; }" : "=r"(a) : "l"(p));
    return a;
}
__device__ __forceinline__ void cp16(uint32_t dst, const void* src) {
    asm volatile("cp.async.cg.shared.global [%0], [%1], 16;" :: "r"(dst), "l"(src));
}
#define CP_COMMIT() asm volatile("cp.async.commit_group;" ::: "memory")
#define CP_WAIT1()  asm volatile("cp.async.wait_group 1;"  ::: "memory")

__device__ __forceinline__ void ldm_x4(uint32_t& r0, uint32_t& r1, uint32_t& r2, uint32_t& r3,
                                       uint32_t a) {
    asm volatile("ldmatrix.sync.aligned.m8n8.x4.shared.b16 {%0,%1,%2,%3}, [%4];"
                 : "=r"(r0), "=r"(r1), "=r"(r2), "=r"(r3) : "r"(a));
}
__device__ __forceinline__ void ldm_x4t(uint32_t& r0, uint32_t& r1, uint32_t& r2, uint32_t& r3,
                                        uint32_t a) {
    asm volatile("ldmatrix.sync.aligned.m8n8.x4.trans.shared.b16 {%0,%1,%2,%3}, [%4];"
                 : "=r"(r0), "=r"(r1), "=r"(r2), "=r"(r3) : "r"(a));
}
__device__ __forceinline__ void mma16816(float* c, const uint32_t* a, uint32_t b0, uint32_t b1) {
    asm volatile(
        "mma.sync.aligned.m16n8k16.row.col.f32.bf16.bf16.f32 "
        "{%0,%1,%2,%3}, {%4,%5,%6,%7}, {%8,%9}, {%0,%1,%2,%3};"
        : "+f"(c[0]), "+f"(c[1]), "+f"(c[2]), "+f"(c[3])
        : "r"(a[0]), "r"(a[1]), "r"(a[2]), "r"(a[3]), "r"(b0), "r"(b1));
}

// ---------------- K1: degrees -> rsqrt(max(sum,1)) ----------------
__global__ void deg_kernel(const float* __restrict__ adj) {
    int bi = blockIdx.x;
    int i  = bi & (NNODE - 1);
    const float4* row = (const float4*)(adj + (size_t)bi * (NNODE * NEDGE));
    float4 s = make_float4(0.f, 0.f, 0.f, 0.f);
    for (int j = threadIdx.x; j < NNODE; j += blockDim.x) {
        float4 v = row[j];
        if (j == i) v = make_float4(1.f, 1.f, 1.f, 1.f);
        s.x += v.x; s.y += v.y; s.z += v.z; s.w += v.w;
    }
    for (int o = 16; o > 0; o >>= 1) {
        s.x += __shfl_down_sync(0xffffffffu, s.x, o);
        s.y += __shfl_down_sync(0xffffffffu, s.y, o);
        s.z += __shfl_down_sync(0xffffffffu, s.z, o);
        s.w += __shfl_down_sync(0xffffffffu, s.w, o);
    }
    __shared__ float4 sh[4];
    int lane = threadIdx.x & 31, w = threadIdx.x >> 5;
    if (lane == 0) sh[w] = s;
    __syncthreads();
    if (threadIdx.x == 0) {
        float4 t = sh[0];
        t.x += sh[1].x + sh[2].x + sh[3].x;
        t.y += sh[1].y + sh[2].y + sh[3].y;
        t.z += sh[1].z + sh[2].z + sh[3].z;
        t.w += sh[1].w + sh[2].w + sh[3].w;
        float4 r;
        r.x = rsqrtf(fmaxf(t.x, 1.f));
        r.y = rsqrtf(fmaxf(t.y, 1.f));
        r.z = rsqrtf(fmaxf(t.z, 1.f));
        r.w = rsqrtf(fmaxf(t.w, 1.f));
        ((float4*)g_deg)[bi] = r;
    }
}

// ---------------- K2: collapsed normalized adjacency -> bf16 hi/lo ----------------
__global__ void buildA_kernel(const float* __restrict__ adj) {
    size_t t = (size_t)blockIdx.x * blockDim.x + threadIdx.x;   // over B*N*N
    int j = (int)(t & (NNODE - 1));
    int i = (int)((t >> 9) & (NNODE - 1));
    int b = (int)(t >> 18);
    float4 a = ((const float4*)adj)[t];
    if (i == j) a = make_float4(1.f, 1.f, 1.f, 1.f);
    float4 di = ((const float4*)g_deg)[b * NNODE + i];
    float4 dj = ((const float4*)g_deg)[b * NNODE + j];
    float v = a.x * di.x * dj.x + a.y * di.y * dj.y + a.z * di.z * dj.z + a.w * di.w * dj.w;
    __nv_bfloat16 hi = __float2bfloat16(v);
    g_Ahi[t] = hi;
    g_Alo[t] = __float2bfloat16(v - __bfloat162float(hi));
}

// ---------------- K3: lin: H[b][k][n] (hi/lo bf16) = X @ W ----------------
__global__ __launch_bounds__(256)
void lin_kernel(const float* __restrict__ X, const float* __restrict__ W, int K,
                __nv_bfloat16* __restrict__ Hhi, __nv_bfloat16* __restrict__ Hlo) {
    int b  = blockIdx.x >> 2;
    int rt = blockIdx.x & 3;
    const float* Xb = X + (size_t)(b * NNODE + rt * 128) * K;

    __shared__ float As[8][128];
    __shared__ float Bs[8][128];

    int tid = threadIdx.x;
    int tx = tid & 15, ty = tid >> 4;

    float acc[8][8];
#pragma unroll
    for (int u = 0; u < 8; u++)
#pragma unroll
        for (int v = 0; v < 8; v++) acc[u][v] = 0.f;

    int arow = tid >> 1, acol = (tid & 1) * 4;
    int brow = tid >> 5, bcol = (tid & 31) * 4;

    for (int k0 = 0; k0 < K; k0 += 8) {
        float4 a = *(const float4*)(Xb + (size_t)arow * K + k0 + acol);
        As[acol + 0][arow] = a.x;
        As[acol + 1][arow] = a.y;
        As[acol + 2][arow] = a.z;
        As[acol + 3][arow] = a.w;
        *(float4*)(&Bs[brow][bcol]) = *(const float4*)(W + (size_t)(k0 + brow) * CHID + bcol);
        __syncthreads();
#pragma unroll
        for (int kk = 0; kk < 8; kk++) {
            float ra[8], rb[8];
            *(float4*)(ra)     = *(const float4*)(&As[kk][ty * 8]);
            *(float4*)(ra + 4) = *(const float4*)(&As[kk][ty * 8 + 4]);
            *(float4*)(rb)     = *(const float4*)(&Bs[kk][tx * 8]);
            *(float4*)(rb + 4) = *(const float4*)(&Bs[kk][tx * 8 + 4]);
#pragma unroll
            for (int u = 0; u < 8; u++)
#pragma unroll
                for (int v = 0; v < 8; v++)
                    acc[u][v] = fmaf(ra[u], rb[v], acc[u][v]);
        }
        __syncthreads();
    }

    // split-bf16 write, natural [row][col] layout (rows are k of the next GEMM)
#pragma unroll
    for (int u = 0; u < 8; u++) {
        int row = ty * 8 + u;
        size_t base = ((size_t)(b * NNODE + rt * 128 + row)) * CHID + tx * 8;
        __nv_bfloat16 hi8[8], lo8[8];
#pragma unroll
        for (int v = 0; v < 8; v++) {
            float val = acc[u][v];
            __nv_bfloat16 hi = __float2bfloat16(val);
            hi8[v] = hi;
            lo8[v] = __float2bfloat16(val - __bfloat162float(hi));
        }
        *(uint4*)(Hhi + base) = *(const uint4*)hi8;
        *(uint4*)(Hlo + base) = *(const uint4*)lo8;
    }
}

// ---------------- K4: mma.sync GCN GEMM: hout = silu(mask*(A@H + bias)) ----------------
__device__ __forceinline__ void load_chunk(uint32_t st, int c, int tid,
                                           const char* Ah, const char* Al,
                                           const char* Bh, const char* Bl) {
#pragma unroll
    for (int i = 0; i < 4; i++) {
        int item = tid + i * 256;           // 0..1023
        int row = item >> 3, seg = item & 7;
        uint32_t so = (uint32_t)(row * ASTR + seg * 16);
        size_t   go = (size_t)row * (NNODE * 2) + (size_t)c * (KC * 2) + seg * 16;
        cp16(st + OFF_AHI + so, Ah + go);
        cp16(st + OFF_ALO + so, Al + go);
    }
#pragma unroll
    for (int i = 0; i < 4; i++) {
        int item = tid + i * 256;           // 0..1023
        int kr = item >> 4, seg = item & 15;
        uint32_t so = (uint32_t)(kr * HSTR + seg * 16);
        size_t   go = (size_t)(c * KC + kr) * (CHID * 2) + seg * 16;
        cp16(st + OFF_HHI + so, Bh + go);
        cp16(st + OFF_HLO + so, Bl + go);
    }
    CP_COMMIT();
}

__global__ __launch_bounds__(256)
void gcn_mma_kernel(const __nv_bfloat16* __restrict__ Ahi, const __nv_bfloat16* __restrict__ Alo,
                    const __nv_bfloat16* __restrict__ Hhi, const __nv_bfloat16* __restrict__ Hlo,
                    const float* __restrict__ bias, const int* __restrict__ mask,
                    float* __restrict__ Hout) {
    extern __shared__ char smem[];
    uint32_t sb = smem_u32(smem);
    int tid = threadIdx.x;
    int wid = tid >> 5, lane = tid & 31;
    int warpM = wid >> 2, warpN = wid & 3;

    // ldmatrix lane address components (within-tile, stage-relative)
    uint32_t aRow = (uint32_t)((warpM * 64 + (lane & 15)) * ASTR + (lane >> 4) * 16);
    uint32_t bRow = (uint32_t)(((lane & 7) + ((lane >> 3) & 1) * 8) * HSTR
                               + (warpN * 32 + ((lane >> 4) & 1) * 8) * 2);

    for (int ti = 0; ti < 2; ti++) {
        int t = blockIdx.x * 2 + ti;
        int b = t >> 2, rt = t & 3;
        const char* Ah = (const char*)Ahi + ((size_t)(b * NNODE + rt * 128)) * (NNODE * 2);
        const char* Al = (const char*)Alo + ((size_t)(b * NNODE + rt * 128)) * (NNODE * 2);
        const char* Bh = (const char*)Hhi + ((size_t)b * NNODE) * (CHID * 2);
        const char* Bl = (const char*)Hlo + ((size_t)b * NNODE) * (CHID * 2);

        __syncthreads();   // previous tile's smem reads complete before refill
        load_chunk(sb, 0, tid, Ah, Al, Bh, Bl);
        load_chunk(sb + STAGEB, 1, tid, Ah, Al, Bh, Bl);

        float acc[4][4][4];
#pragma unroll
        for (int m = 0; m < 4; m++)
#pragma unroll
            for (int n = 0; n < 4; n++)
#pragma unroll
                for (int k = 0; k < 4; k++) acc[m][n][k] = 0.f;

        for (int c = 0; c < NCHUNK; c++) {
            CP_WAIT1();
            __syncthreads();
            uint32_t st = sb + (uint32_t)(c & 1) * STAGEB;
#pragma unroll
            for (int ks = 0; ks < 4; ks++) {
                uint32_t ahi[4][4], alo[4][4];
#pragma unroll
                for (int mt = 0; mt < 4; mt++) {
                    uint32_t ad = st + aRow + (uint32_t)(mt * 16 * ASTR + ks * 32);
                    ldm_x4(ahi[mt][0], ahi[mt][1], ahi[mt][2], ahi[mt][3], ad + OFF_AHI);
                    ldm_x4(alo[mt][0], alo[mt][1], alo[mt][2], alo[mt][3], ad + OFF_ALO);
                }
                uint32_t bhi[2][4], blo[2][4];
#pragma unroll
                for (int ng = 0; ng < 2; ng++) {
                    uint32_t bd = st + bRow + (uint32_t)(ks * 16 * HSTR + ng * 32);
                    ldm_x4t(bhi[ng][0], bhi[ng][1], bhi[ng][2], bhi[ng][3], bd + OFF_HHI);
                    ldm_x4t(blo[ng][0], blo[ng][1], blo[ng][2], blo[ng][3], bd + OFF_HLO);
                }
#pragma unroll
                for (int mt = 0; mt < 4; mt++)
#pragma unroll
                    for (int nt = 0; nt < 4; nt++) {
                        int ng = nt >> 1, hf = nt & 1;
                        mma16816(acc[mt][nt], ahi[mt], bhi[ng][hf * 2], bhi[ng][hf * 2 + 1]);
                        mma16816(acc[mt][nt], ahi[mt], blo[ng][hf * 2], blo[ng][hf * 2 + 1]);
                        mma16816(acc[mt][nt], alo[mt], bhi[ng][hf * 2], bhi[ng][hf * 2 + 1]);
                    }
            }
            __syncthreads();
            if (c + 2 < NCHUNK)
                load_chunk(sb + (uint32_t)(c & 1) * STAGEB, c + 2, tid, Ah, Al, Bh, Bl);
            else
                CP_COMMIT();   // empty group keeps wait accounting constant
        }

        // epilogue: bias + mask + silu -> fp32
        int rowBase = b * NNODE + rt * 128 + warpM * 64;
        float* Ob = Hout + (size_t)(b * NNODE + rt * 128 + warpM * 64) * CHID;
#pragma unroll
        for (int mt = 0; mt < 4; mt++) {
            int r0 = mt * 16 + (lane >> 2);
            float m0 = (float)mask[rowBase + r0];
            float m1 = (float)mask[rowBase + r0 + 8];
#pragma unroll
            for (int nt = 0; nt < 4; nt++) {
                int col = warpN * 32 + nt * 8 + (lane & 3) * 2;
                float b0v = bias[col], b1v = bias[col + 1];
                float z0 = (acc[mt][nt][0] + b0v) * m0;
                float z1 = (acc[mt][nt][1] + b1v) * m0;
                float z2 = (acc[mt][nt][2] + b0v) * m1;
                float z3 = (acc[mt][nt][3] + b1v) * m1;
                float2 o0 = make_float2(z0 / (1.f + __expf(-z0)), z1 / (1.f + __expf(-z1)));
                float2 o1 = make_float2(z2 / (1.f + __expf(-z2)), z3 / (1.f + __expf(-z3)));
                *(float2*)(Ob + (size_t)r0 * CHID + col)       = o0;
                *(float2*)(Ob + (size_t)(r0 + 8) * CHID + col) = o1;
            }
        }
    }
}

// ---------------- K5: mean pool + MLP head ----------------
__global__ void head_kernel(const float* __restrict__ hfinal,
                            const float* __restrict__ Wl1, const float* __restrict__ bl1,
                            const float* __restrict__ Wl2, const float* __restrict__ bl2,
                            float* __restrict__ out) {
    int b = blockIdx.x;
    int c = threadIdx.x;     // 128
    int w = threadIdx.y;     // 4
    const float* base = hfinal + (size_t)b * NNODE * CHID;
    float s = 0.f;
    for (int i = w; i < NNODE; i += 4) s += base[(size_t)i * CHID + c];
    __shared__ float red[4][CHID];
    red[w][c] = s;
    __syncthreads();
    __shared__ float g[CHID], g1[CHID];
    if (w == 0) {
        g[c] = (red[0][c] + red[1][c] + red[2][c] + red[3][c]) * (1.0f / NNODE);
    }
    __syncthreads();
    if (w == 0) {
        float acc = bl1[c];
        for (int k = 0; k < CHID; k++) acc = fmaf(g[k], Wl1[k * CHID + c], acc);
        g1[c] = acc / (1.f + __expf(-acc));
    }
    __syncthreads();
    if (w == 0 && c < COUT) {
        float acc2 = bl2[c];
        for (int k = 0; k < CHID; k++) acc2 = fmaf(g1[k], Wl2[k * COUT + c], acc2);
        out[b * COUT + c] = acc2;
    }
}

// ---------------- launch ----------------
extern "C" void kernel_launch(void* const* d_in, const int* in_sizes, int n_in,
                              void* d_out, int out_size) {
    const float* x    = (const float*)d_in[0];
    const float* adj  = (const float*)d_in[1];
    const int*   mask = (const int*)  d_in[2];
    const float* W0   = (const float*)d_in[3];
    const float* b0   = (const float*)d_in[4];
    const float* W1   = (const float*)d_in[5];
    const float* b1   = (const float*)d_in[6];
    const float* Wl1  = (const float*)d_in[7];
    const float* bl1  = (const float*)d_in[8];
    const float* Wl2  = (const float*)d_in[9];
    const float* bl2  = (const float*)d_in[10];
    float* out = (float*)d_out;

    __nv_bfloat16 *dAhi, *dAlo, *dHhi, *dHlo;
    float *dHout;
    cudaGetSymbolAddress((void**)&dAhi, g_Ahi);
    cudaGetSymbolAddress((void**)&dAlo, g_Alo);
    cudaGetSymbolAddress((void**)&dHhi, g_Hhi);
    cudaGetSymbolAddress((void**)&dHlo, g_Hlo);
    cudaGetSymbolAddress((void**)&dHout, g_hout);

    static int smem_set = 0;
    if (!smem_set) {
        cudaFuncSetAttribute(gcn_mma_kernel, cudaFuncAttributeMaxDynamicSharedMemorySize, SMEM_DYN);
        smem_set = 1;
    }

    // 1) degrees
    deg_kernel<<<BATCH * NNODE, 128>>>(adj);
    // 2) collapsed normalized adjacency (bf16 hi/lo)
    buildA_kernel<<<(BATCH * NNODE * NNODE) / 256, 256>>>(adj);
    // 3) H = x @ W0 (split bf16)
    lin_kernel<<<BATCH * 4, 256>>>(x, W0, CIN, dHhi, dHlo);
    // 4) layer 1 (tensor cores via mma.sync)
    gcn_mma_kernel<<<BATCH * 2, 256, SMEM_DYN>>>(dAhi, dAlo, dHhi, dHlo, b0, mask, dHout);
    // 5) H = h1 @ W1 (split bf16)
    lin_kernel<<<BATCH * 4, 256>>>(dHout, W1, CHID, dHhi, dHlo);
    // 6) layer 2
    gcn_mma_kernel<<<BATCH * 2, 256, SMEM_DYN>>>(dAhi, dAlo, dHhi, dHlo, b1, mask, dHout);
    // 7) mean pool + MLP head
    head_kernel<<<BATCH, dim3(CHID, 4)>>>(dHout, Wl1, bl1, Wl2, bl2, out);
}

// round 5
// speedup vs baseline: 1.8376x; 1.0814x over previous
#include <cuda_runtime.h>
#include <cuda_bf16.h>
#include <cstdint>
#include <math.h>

#define BATCH 64
#define NNODE 512
#define NEDGE 4
#define CIN   64
#define CHID  128
#define COUT  16

// ---- mma.sync GEMM tiling ----
#define KC 32                               // K per pipeline chunk
#define NCHUNK (NNODE / KC)                 // 16
#define ASTR 80                             // A smem row stride bytes (32 bf16 + 16 pad)
#define HSTR 272                            // H smem row stride bytes (128 bf16 + 8 pad)
#define OFF_AHI 0
#define OFF_ALO (128 * ASTR)                // 10240
#define OFF_HHI (2 * 128 * ASTR)            // 20480
#define OFF_HLO (2 * 128 * ASTR + KC * HSTR)
#define STAGEB  (2 * 128 * ASTR + 2 * KC * HSTR)   // 37888
#define SMEM_DYN (2 * STAGEB)                       // 75776 -> 2 CTAs/SM

// ---------------- device scratch ----------------
__device__ float          g_deg [BATCH * NNODE * NEDGE];
__device__ __nv_bfloat16  g_Ahi [(size_t)BATCH * NNODE * NNODE];   // 32MB
__device__ __nv_bfloat16  g_Alo [(size_t)BATCH * NNODE * NNODE];   // 32MB
__device__ __nv_bfloat16  g_Hhi [(size_t)BATCH * NNODE * CHID];    // 8MB  [b][k][n]
__device__ __nv_bfloat16  g_Hlo [(size_t)BATCH * NNODE * CHID];    // 8MB
__device__ float          g_hout[(size_t)BATCH * NNODE * CHID];    // 16MB

// ---------------- PTX helpers ----------------
__device__ __forceinline__ uint32_t smem_u32(const void* p) {
    uint32_t a;
    asm("{ .reg .u64 t; cvta.to.shared.u64 t, %1; cvt.u32.u64 %0, t; }" : "=r"(a) : "l"(p));
    return a;
}
__device__ __forceinline__ void cp16(uint32_t dst, const void* src) {
    asm volatile("cp.async.cg.shared.global [%0], [%1], 16;" :: "r"(dst), "l"(src));
}
#define CP_COMMIT() asm volatile("cp.async.commit_group;" ::: "memory")
#define CP_WAIT1()  asm volatile("cp.async.wait_group 1;"  ::: "memory")

__device__ __forceinline__ void ldm_x4(uint32_t& r0, uint32_t& r1, uint32_t& r2, uint32_t& r3,
                                       uint32_t a) {
    asm volatile("ldmatrix.sync.aligned.m8n8.x4.shared.b16 {%0,%1,%2,%3}, [%4];"
                 : "=r"(r0), "=r"(r1), "=r"(r2), "=r"(r3) : "r"(a));
}
__device__ __forceinline__ void ldm_x4t(uint32_t& r0, uint32_t& r1, uint32_t& r2, uint32_t& r3,
                                        uint32_t a) {
    asm volatile("ldmatrix.sync.aligned.m8n8.x4.trans.shared.b16 {%0,%1,%2,%3}, [%4];"
                 : "=r"(r0), "=r"(r1), "=r"(r2), "=r"(r3) : "r"(a));
}
__device__ __forceinline__ void mma16816(float* c, const uint32_t* a, uint32_t b0, uint32_t b1) {
    asm volatile(
        "mma.sync.aligned.m16n8k16.row.col.f32.bf16.bf16.f32 "
        "{%0,%1,%2,%3}, {%4,%5,%6,%7}, {%8,%9}, {%0,%1,%2,%3};"
        : "+f"(c[0]), "+f"(c[1]), "+f"(c[2]), "+f"(c[3])
        : "r"(a[0]), "r"(a[1]), "r"(a[2]), "r"(a[3]), "r"(b0), "r"(b1));
}

// ---------------- K1: degrees -> rsqrt(max(sum,1)), MLP=4 ----------------
__global__ void deg_kernel(const float* __restrict__ adj) {
    int bi = blockIdx.x;
    int i  = bi & (NNODE - 1);
    const float4* row = (const float4*)(adj + (size_t)bi * (NNODE * NEDGE));
    int j = threadIdx.x;
    // 4 independent loads in flight
    float4 v0 = row[j];
    float4 v1 = row[j + 128];
    float4 v2 = row[j + 256];
    float4 v3 = row[j + 384];
    if (j == i)         v0 = make_float4(1.f, 1.f, 1.f, 1.f);
    if (j + 128 == i)   v1 = make_float4(1.f, 1.f, 1.f, 1.f);
    if (j + 256 == i)   v2 = make_float4(1.f, 1.f, 1.f, 1.f);
    if (j + 384 == i)   v3 = make_float4(1.f, 1.f, 1.f, 1.f);
    float4 s;
    s.x = (v0.x + v1.x) + (v2.x + v3.x);
    s.y = (v0.y + v1.y) + (v2.y + v3.y);
    s.z = (v0.z + v1.z) + (v2.z + v3.z);
    s.w = (v0.w + v1.w) + (v2.w + v3.w);
    for (int o = 16; o > 0; o >>= 1) {
        s.x += __shfl_down_sync(0xffffffffu, s.x, o);
        s.y += __shfl_down_sync(0xffffffffu, s.y, o);
        s.z += __shfl_down_sync(0xffffffffu, s.z, o);
        s.w += __shfl_down_sync(0xffffffffu, s.w, o);
    }
    __shared__ float4 sh[4];
    int lane = threadIdx.x & 31, w = threadIdx.x >> 5;
    if (lane == 0) sh[w] = s;
    __syncthreads();
    if (threadIdx.x == 0) {
        float4 t = sh[0];
        t.x += sh[1].x + sh[2].x + sh[3].x;
        t.y += sh[1].y + sh[2].y + sh[3].y;
        t.z += sh[1].z + sh[2].z + sh[3].z;
        t.w += sh[1].w + sh[2].w + sh[3].w;
        float4 r;
        r.x = rsqrtf(fmaxf(t.x, 1.f));
        r.y = rsqrtf(fmaxf(t.y, 1.f));
        r.z = rsqrtf(fmaxf(t.z, 1.f));
        r.w = rsqrtf(fmaxf(t.w, 1.f));
        ((float4*)g_deg)[bi] = r;
    }
}

// ---------------- K2: collapsed adjacency -> bf16 hi/lo, 4 elems/thread ----------------
__global__ void buildA_kernel(const float* __restrict__ adj) {
    // reverse block order: tail of adj is still hot in L2 from deg_kernel
    size_t blk = (size_t)(gridDim.x - 1 - blockIdx.x);
    size_t t0 = (blk * blockDim.x + threadIdx.x) * 4;          // element index, 4 consecutive j
    int j = (int)(t0 & (NNODE - 1));
    int i = (int)((t0 >> 9) & (NNODE - 1));
    int b = (int)(t0 >> 18);
    const float4* ap = (const float4*)adj + t0;
    float4 di = ((const float4*)g_deg)[b * NNODE + i];
    const float4* djp = ((const float4*)g_deg) + b * NNODE + j;
    __nv_bfloat16 hi4[4], lo4[4];
#pragma unroll
    for (int e = 0; e < 4; e++) {
        float4 a = ap[e];
        if (j + e == i) a = make_float4(1.f, 1.f, 1.f, 1.f);
        float4 dj = djp[e];
        float v = a.x * di.x * dj.x + a.y * di.y * dj.y + a.z * di.z * dj.z + a.w * di.w * dj.w;
        __nv_bfloat16 hi = __float2bfloat16(v);
        hi4[e] = hi;
        lo4[e] = __float2bfloat16(v - __bfloat162float(hi));
    }
    *(uint2*)(g_Ahi + t0) = *(const uint2*)hi4;
    *(uint2*)(g_Alo + t0) = *(const uint2*)lo4;
}

// ---------------- K3: lin: H[b][k][n] (hi/lo bf16) = X @ W ----------------
__global__ __launch_bounds__(256)
void lin_kernel(const float* __restrict__ X, const float* __restrict__ W, int K,
                __nv_bfloat16* __restrict__ Hhi, __nv_bfloat16* __restrict__ Hlo) {
    int b  = blockIdx.x >> 2;
    int rt = blockIdx.x & 3;
    const float* Xb = X + (size_t)(b * NNODE + rt * 128) * K;

    __shared__ float As[8][128];
    __shared__ float Bs[8][128];

    int tid = threadIdx.x;
    int tx = tid & 15, ty = tid >> 4;

    float acc[8][8];
#pragma unroll
    for (int u = 0; u < 8; u++)
#pragma unroll
        for (int v = 0; v < 8; v++) acc[u][v] = 0.f;

    int arow = tid >> 1, acol = (tid & 1) * 4;
    int brow = tid >> 5, bcol = (tid & 31) * 4;

    for (int k0 = 0; k0 < K; k0 += 8) {
        float4 a = *(const float4*)(Xb + (size_t)arow * K + k0 + acol);
        As[acol + 0][arow] = a.x;
        As[acol + 1][arow] = a.y;
        As[acol + 2][arow] = a.z;
        As[acol + 3][arow] = a.w;
        *(float4*)(&Bs[brow][bcol]) = *(const float4*)(W + (size_t)(k0 + brow) * CHID + bcol);
        __syncthreads();
#pragma unroll
        for (int kk = 0; kk < 8; kk++) {
            float ra[8], rb[8];
            *(float4*)(ra)     = *(const float4*)(&As[kk][ty * 8]);
            *(float4*)(ra + 4) = *(const float4*)(&As[kk][ty * 8 + 4]);
            *(float4*)(rb)     = *(const float4*)(&Bs[kk][tx * 8]);
            *(float4*)(rb + 4) = *(const float4*)(&Bs[kk][tx * 8 + 4]);
#pragma unroll
            for (int u = 0; u < 8; u++)
#pragma unroll
                for (int v = 0; v < 8; v++)
                    acc[u][v] = fmaf(ra[u], rb[v], acc[u][v]);
        }
        __syncthreads();
    }

#pragma unroll
    for (int u = 0; u < 8; u++) {
        int row = ty * 8 + u;
        size_t base = ((size_t)(b * NNODE + rt * 128 + row)) * CHID + tx * 8;
        __nv_bfloat16 hi8[8], lo8[8];
#pragma unroll
        for (int v = 0; v < 8; v++) {
            float val = acc[u][v];
            __nv_bfloat16 hi = __float2bfloat16(val);
            hi8[v] = hi;
            lo8[v] = __float2bfloat16(val - __bfloat162float(hi));
        }
        *(uint4*)(Hhi + base) = *(const uint4*)hi8;
        *(uint4*)(Hlo + base) = *(const uint4*)lo8;
    }
}

// ---------------- K4: mma.sync GCN GEMM: hout = silu(mask*(A@H + bias)) ----------------
__device__ __forceinline__ void load_chunk(uint32_t st, int c, int tid,
                                           const char* Ah, const char* Al,
                                           const char* Bh, const char* Bl) {
    // A: 128 rows x 64B (KC=32 bf16) = 512 x 16B items, 2 per thread
#pragma unroll
    for (int i = 0; i < 2; i++) {
        int item = tid + i * 256;
        int row = item >> 2, seg = item & 3;
        uint32_t so = (uint32_t)(row * ASTR + seg * 16);
        size_t   go = (size_t)row * (NNODE * 2) + (size_t)c * (KC * 2) + seg * 16;
        cp16(st + OFF_AHI + so, Ah + go);
        cp16(st + OFF_ALO + so, Al + go);
    }
    // H: 32 rows x 256B = 512 x 16B items, 2 per thread
#pragma unroll
    for (int i = 0; i < 2; i++) {
        int item = tid + i * 256;
        int kr = item >> 4, seg = item & 15;
        uint32_t so = (uint32_t)(kr * HSTR + seg * 16);
        size_t   go = (size_t)(c * KC + kr) * (CHID * 2) + seg * 16;
        cp16(st + OFF_HHI + so, Bh + go);
        cp16(st + OFF_HLO + so, Bl + go);
    }
    CP_COMMIT();
}

__global__ __launch_bounds__(256, 2)
void gcn_mma_kernel(const __nv_bfloat16* __restrict__ Ahi, const __nv_bfloat16* __restrict__ Alo,
                    const __nv_bfloat16* __restrict__ Hhi, const __nv_bfloat16* __restrict__ Hlo,
                    const float* __restrict__ bias, const int* __restrict__ mask,
                    float* __restrict__ Hout) {
    extern __shared__ char smem[];
    uint32_t sb = smem_u32(smem);
    int tid = threadIdx.x;
    int wid = tid >> 5, lane = tid & 31;
    int warpM = wid >> 2, warpN = wid & 3;

    int b = blockIdx.x >> 2, rt = blockIdx.x & 3;
    const char* Ah = (const char*)Ahi + ((size_t)(b * NNODE + rt * 128)) * (NNODE * 2);
    const char* Al = (const char*)Alo + ((size_t)(b * NNODE + rt * 128)) * (NNODE * 2);
    const char* Bh = (const char*)Hhi + ((size_t)b * NNODE) * (CHID * 2);
    const char* Bl = (const char*)Hlo + ((size_t)b * NNODE) * (CHID * 2);

    uint32_t aRow = (uint32_t)((warpM * 64 + (lane & 15)) * ASTR + (lane >> 4) * 16);
    uint32_t bRow = (uint32_t)(((lane & 7) + ((lane >> 3) & 1) * 8) * HSTR
                               + (warpN * 32 + ((lane >> 4) & 1) * 8) * 2);

    load_chunk(sb, 0, tid, Ah, Al, Bh, Bl);
    load_chunk(sb + STAGEB, 1, tid, Ah, Al, Bh, Bl);

    float acc[4][4][4];
#pragma unroll
    for (int m = 0; m < 4; m++)
#pragma unroll
        for (int n = 0; n < 4; n++)
#pragma unroll
            for (int k = 0; k < 4; k++) acc[m][n][k] = 0.f;

    for (int c = 0; c < NCHUNK; c++) {
        CP_WAIT1();
        __syncthreads();
        uint32_t st = sb + (uint32_t)(c & 1) * STAGEB;
#pragma unroll
        for (int ks = 0; ks < KC / 16; ks++) {
            uint32_t ahi[4][4], alo[4][4];
#pragma unroll
            for (int mt = 0; mt < 4; mt++) {
                uint32_t ad = st + aRow + (uint32_t)(mt * 16 * ASTR + ks * 32);
                ldm_x4(ahi[mt][0], ahi[mt][1], ahi[mt][2], ahi[mt][3], ad + OFF_AHI);
                ldm_x4(alo[mt][0], alo[mt][1], alo[mt][2], alo[mt][3], ad + OFF_ALO);
            }
            uint32_t bhi[2][4], blo[2][4];
#pragma unroll
            for (int ng = 0; ng < 2; ng++) {
                uint32_t bd = st + bRow + (uint32_t)(ks * 16 * HSTR + ng * 32);
                ldm_x4t(bhi[ng][0], bhi[ng][1], bhi[ng][2], bhi[ng][3], bd + OFF_HHI);
                ldm_x4t(blo[ng][0], blo[ng][1], blo[ng][2], blo[ng][3], bd + OFF_HLO);
            }
#pragma unroll
            for (int mt = 0; mt < 4; mt++)
#pragma unroll
                for (int nt = 0; nt < 4; nt++) {
                    int ng = nt >> 1, hf = nt & 1;
                    mma16816(acc[mt][nt], ahi[mt], bhi[ng][hf * 2], bhi[ng][hf * 2 + 1]);
                    mma16816(acc[mt][nt], ahi[mt], blo[ng][hf * 2], blo[ng][hf * 2 + 1]);
                    mma16816(acc[mt][nt], alo[mt], bhi[ng][hf * 2], bhi[ng][hf * 2 + 1]);
                }
        }
        __syncthreads();
        if (c + 2 < NCHUNK)
            load_chunk(sb + (uint32_t)(c & 1) * STAGEB, c + 2, tid, Ah, Al, Bh, Bl);
        else
            CP_COMMIT();   // keep wait_group accounting constant
    }

    // epilogue: bias + mask + silu -> fp32
    int rowBase = b * NNODE + rt * 128 + warpM * 64;
    float* Ob = Hout + (size_t)rowBase * CHID;
#pragma unroll
    for (int mt = 0; mt < 4; mt++) {
        int r0 = mt * 16 + (lane >> 2);
        float m0 = (float)mask[rowBase + r0];
        float m1 = (float)mask[rowBase + r0 + 8];
#pragma unroll
        for (int nt = 0; nt < 4; nt++) {
            int col = warpN * 32 + nt * 8 + (lane & 3) * 2;
            float b0v = bias[col], b1v = bias[col + 1];
            float z0 = (acc[mt][nt][0] + b0v) * m0;
            float z1 = (acc[mt][nt][1] + b1v) * m0;
            float z2 = (acc[mt][nt][2] + b0v) * m1;
            float z3 = (acc[mt][nt][3] + b1v) * m1;
            float2 o0 = make_float2(z0 / (1.f + __expf(-z0)), z1 / (1.f + __expf(-z1)));
            float2 o1 = make_float2(z2 / (1.f + __expf(-z2)), z3 / (1.f + __expf(-z3)));
            *(float2*)(Ob + (size_t)r0 * CHID + col)       = o0;
            *(float2*)(Ob + (size_t)(r0 + 8) * CHID + col) = o1;
        }
    }
}

// ---------------- K5: mean pool + MLP head ----------------
__global__ void head_kernel(const float* __restrict__ hfinal,
                            const float* __restrict__ Wl1, const float* __restrict__ bl1,
                            const float* __restrict__ Wl2, const float* __restrict__ bl2,
                            float* __restrict__ out) {
    int b = blockIdx.x;
    int c = threadIdx.x;     // 128
    int w = threadIdx.y;     // 4
    const float* base = hfinal + (size_t)b * NNODE * CHID;
    float s = 0.f;
    for (int i = w; i < NNODE; i += 4) s += base[(size_t)i * CHID + c];
    __shared__ float red[4][CHID];
    red[w][c] = s;
    __syncthreads();
    __shared__ float g[CHID], g1[CHID];
    if (w == 0) {
        g[c] = (red[0][c] + red[1][c] + red[2][c] + red[3][c]) * (1.0f / NNODE);
    }
    __syncthreads();
    if (w == 0) {
        float acc = bl1[c];
        for (int k = 0; k < CHID; k++) acc = fmaf(g[k], Wl1[k * CHID + c], acc);
        g1[c] = acc / (1.f + __expf(-acc));
    }
    __syncthreads();
    if (w == 0 && c < COUT) {
        float acc2 = bl2[c];
        for (int k = 0; k < CHID; k++) acc2 = fmaf(g1[k], Wl2[k * COUT + c], acc2);
        out[b * COUT + c] = acc2;
    }
}

// ---------------- launch ----------------
extern "C" void kernel_launch(void* const* d_in, const int* in_sizes, int n_in,
                              void* d_out, int out_size) {
    const float* x    = (const float*)d_in[0];
    const float* adj  = (const float*)d_in[1];
    const int*   mask = (const int*)  d_in[2];
    const float* W0   = (const float*)d_in[3];
    const float* b0   = (const float*)d_in[4];
    const float* W1   = (const float*)d_in[5];
    const float* b1   = (const float*)d_in[6];
    const float* Wl1  = (const float*)d_in[7];
    const float* bl1  = (const float*)d_in[8];
    const float* Wl2  = (const float*)d_in[9];
    const float* bl2  = (const float*)d_in[10];
    float* out = (float*)d_out;

    __nv_bfloat16 *dAhi, *dAlo, *dHhi, *dHlo;
    float *dHout;
    cudaGetSymbolAddress((void**)&dAhi, g_Ahi);
    cudaGetSymbolAddress((void**)&dAlo, g_Alo);
    cudaGetSymbolAddress((void**)&dHhi, g_Hhi);
    cudaGetSymbolAddress((void**)&dHlo, g_Hlo);
    cudaGetSymbolAddress((void**)&dHout, g_hout);

    static int smem_set = 0;
    if (!smem_set) {
        cudaFuncSetAttribute(gcn_mma_kernel, cudaFuncAttributeMaxDynamicSharedMemorySize, SMEM_DYN);
        smem_set = 1;
    }

    // 1) degrees
    deg_kernel<<<BATCH * NNODE, 128>>>(adj);
    // 2) collapsed normalized adjacency (bf16 hi/lo)
    buildA_kernel<<<(BATCH * NNODE * NNODE) / (256 * 4), 256>>>(adj);
    // 3) H = x @ W0 (split bf16)
    lin_kernel<<<BATCH * 4, 256>>>(x, W0, CIN, dHhi, dHlo);
    // 4) layer 1 (tensor cores via mma.sync)
    gcn_mma_kernel<<<BATCH * 4, 256, SMEM_DYN>>>(dAhi, dAlo, dHhi, dHlo, b0, mask, dHout);
    // 5) H = h1 @ W1 (split bf16)
    lin_kernel<<<BATCH * 4, 256>>>(dHout, W1, CHID, dHhi, dHlo);
    // 6) layer 2
    gcn_mma_kernel<<<BATCH * 4, 256, SMEM_DYN>>>(dAhi, dAlo, dHhi, dHlo, b1, mask, dHout);
    // 7) mean pool + MLP head
    head_kernel<<<BATCH, dim3(CHID, 4)>>>(dHout, Wl1, bl1, Wl2, bl2, out);
}

// round 6
// speedup vs baseline: 1.8426x; 1.0027x over previous
#include <cuda_runtime.h>
#include <cuda_bf16.h>
#include <cstdint>
#include <math.h>

#define BATCH 64
#define NNODE 512
#define NEDGE 4
#define CIN   64
#define CHID  128
#define COUT  16

// ---- mma.sync GEMM tiling ----
#define KC 32                               // K per pipeline chunk
#define NCHUNK (NNODE / KC)                 // 16
#define ASTR 80                             // A smem row stride bytes (32 bf16 + 16 pad)
#define HSTR 272                            // H smem row stride bytes (128 bf16 + 8 pad)
#define OFF_AHI 0
#define OFF_ALO (128 * ASTR)                // 10240
#define OFF_HHI (2 * 128 * ASTR)            // 20480
#define OFF_HLO (2 * 128 * ASTR + KC * HSTR)
#define STAGEB  (2 * 128 * ASTR + 2 * KC * HSTR)   // 37888
#define SMEM_DYN (2 * STAGEB)                       // 75776 -> 2 CTAs/SM

// ---------------- device scratch ----------------
__device__ float          g_deg [BATCH * NNODE * NEDGE];
__device__ __nv_bfloat16  g_Ahi [(size_t)BATCH * NNODE * NNODE];   // 32MB
__device__ __nv_bfloat16  g_Alo [(size_t)BATCH * NNODE * NNODE];   // 32MB
__device__ __nv_bfloat16  g_Hhi [(size_t)BATCH * NNODE * CHID];    // 8MB  [b][k][n]
__device__ __nv_bfloat16  g_Hlo [(size_t)BATCH * NNODE * CHID];    // 8MB
__device__ float          g_hout[(size_t)BATCH * NNODE * CHID];    // 16MB

// ---------------- PTX helpers ----------------
__device__ __forceinline__ uint32_t smem_u32(const void* p) {
    uint32_t a;
    asm("{ .reg .u64 t; cvta.to.shared.u64 t, %1; cvt.u32.u64 %0, t; }" : "=r"(a) : "l"(p));
    return a;
}
__device__ __forceinline__ void cp16(uint32_t dst, const void* src) {
    asm volatile("cp.async.cg.shared.global [%0], [%1], 16;" :: "r"(dst), "l"(src));
}
#define CP_COMMIT() asm volatile("cp.async.commit_group;" ::: "memory")
#define CP_WAIT1()  asm volatile("cp.async.wait_group 1;"  ::: "memory")

__device__ __forceinline__ void ldm_x4(uint32_t& r0, uint32_t& r1, uint32_t& r2, uint32_t& r3,
                                       uint32_t a) {
    asm volatile("ldmatrix.sync.aligned.m8n8.x4.shared.b16 {%0,%1,%2,%3}, [%4];"
                 : "=r"(r0), "=r"(r1), "=r"(r2), "=r"(r3) : "r"(a));
}
__device__ __forceinline__ void ldm_x4t(uint32_t& r0, uint32_t& r1, uint32_t& r2, uint32_t& r3,
                                        uint32_t a) {
    asm volatile("ldmatrix.sync.aligned.m8n8.x4.trans.shared.b16 {%0,%1,%2,%3}, [%4];"
                 : "=r"(r0), "=r"(r1), "=r"(r2), "=r"(r3) : "r"(a));
}
__device__ __forceinline__ void mma16816(float* c, const uint32_t* a, uint32_t b0, uint32_t b1) {
    asm volatile(
        "mma.sync.aligned.m16n8k16.row.col.f32.bf16.bf16.f32 "
        "{%0,%1,%2,%3}, {%4,%5,%6,%7}, {%8,%9}, {%0,%1,%2,%3};"
        : "+f"(c[0]), "+f"(c[1]), "+f"(c[2]), "+f"(c[3])
        : "r"(a[0]), "r"(a[1]), "r"(a[2]), "r"(a[3]), "r"(b0), "r"(b1));
}

// ---------------- K1: degrees -> rsqrt(max(sum,1)), MLP=4 ----------------
__global__ void deg_kernel(const float* __restrict__ adj) {
    int bi = blockIdx.x;
    int i  = bi & (NNODE - 1);
    const float4* row = (const float4*)(adj + (size_t)bi * (NNODE * NEDGE));
    int j = threadIdx.x;
    // 4 independent loads in flight
    float4 v0 = row[j];
    float4 v1 = row[j + 128];
    float4 v2 = row[j + 256];
    float4 v3 = row[j + 384];
    if (j == i)         v0 = make_float4(1.f, 1.f, 1.f, 1.f);
    if (j + 128 == i)   v1 = make_float4(1.f, 1.f, 1.f, 1.f);
    if (j + 256 == i)   v2 = make_float4(1.f, 1.f, 1.f, 1.f);
    if (j + 384 == i)   v3 = make_float4(1.f, 1.f, 1.f, 1.f);
    float4 s;
    s.x = (v0.x + v1.x) + (v2.x + v3.x);
    s.y = (v0.y + v1.y) + (v2.y + v3.y);
    s.z = (v0.z + v1.z) + (v2.z + v3.z);
    s.w = (v0.w + v1.w) + (v2.w + v3.w);
    for (int o = 16; o > 0; o >>= 1) {
        s.x += __shfl_down_sync(0xffffffffu, s.x, o);
        s.y += __shfl_down_sync(0xffffffffu, s.y, o);
        s.z += __shfl_down_sync(0xffffffffu, s.z, o);
        s.w += __shfl_down_sync(0xffffffffu, s.w, o);
    }
    __shared__ float4 sh[4];
    int lane = threadIdx.x & 31, w = threadIdx.x >> 5;
    if (lane == 0) sh[w] = s;
    __syncthreads();
    if (threadIdx.x == 0) {
        float4 t = sh[0];
        t.x += sh[1].x + sh[2].x + sh[3].x;
        t.y += sh[1].y + sh[2].y + sh[3].y;
        t.z += sh[1].z + sh[2].z + sh[3].z;
        t.w += sh[1].w + sh[2].w + sh[3].w;
        float4 r;
        r.x = rsqrtf(fmaxf(t.x, 1.f));
        r.y = rsqrtf(fmaxf(t.y, 1.f));
        r.z = rsqrtf(fmaxf(t.z, 1.f));
        r.w = rsqrtf(fmaxf(t.w, 1.f));
        ((float4*)g_deg)[bi] = r;
    }
}

// ---------------- K2: collapsed adjacency -> bf16 hi/lo, 4 elems/thread ----------------
__global__ void buildA_kernel(const float* __restrict__ adj) {
    // reverse block order: tail of adj is still hot in L2 from deg_kernel
    size_t blk = (size_t)(gridDim.x - 1 - blockIdx.x);
    size_t t0 = (blk * blockDim.x + threadIdx.x) * 4;          // element index, 4 consecutive j
    int j = (int)(t0 & (NNODE - 1));
    int i = (int)((t0 >> 9) & (NNODE - 1));
    int b = (int)(t0 >> 18);
    const float4* ap = (const float4*)adj + t0;
    float4 di = ((const float4*)g_deg)[b * NNODE + i];
    const float4* djp = ((const float4*)g_deg) + b * NNODE + j;
    __nv_bfloat16 hi4[4], lo4[4];
#pragma unroll
    for (int e = 0; e < 4; e++) {
        float4 a = ap[e];
        if (j + e == i) a = make_float4(1.f, 1.f, 1.f, 1.f);
        float4 dj = djp[e];
        float v = a.x * di.x * dj.x + a.y * di.y * dj.y + a.z * di.z * dj.z + a.w * di.w * dj.w;
        __nv_bfloat16 hi = __float2bfloat16(v);
        hi4[e] = hi;
        lo4[e] = __float2bfloat16(v - __bfloat162float(hi));
    }
    *(uint2*)(g_Ahi + t0) = *(const uint2*)hi4;
    *(uint2*)(g_Alo + t0) = *(const uint2*)lo4;
}

// ---------------- K3: lin: H[b][k][n] (hi/lo bf16) = X @ W ----------------
__global__ __launch_bounds__(256)
void lin_kernel(const float* __restrict__ X, const float* __restrict__ W, int K,
                __nv_bfloat16* __restrict__ Hhi, __nv_bfloat16* __restrict__ Hlo) {
    int b  = blockIdx.x >> 2;
    int rt = blockIdx.x & 3;
    const float* Xb = X + (size_t)(b * NNODE + rt * 128) * K;

    __shared__ float As[8][128];
    __shared__ float Bs[8][128];

    int tid = threadIdx.x;
    int tx = tid & 15, ty = tid >> 4;

    float acc[8][8];
#pragma unroll
    for (int u = 0; u < 8; u++)
#pragma unroll
        for (int v = 0; v < 8; v++) acc[u][v] = 0.f;

    int arow = tid >> 1, acol = (tid & 1) * 4;
    int brow = tid >> 5, bcol = (tid & 31) * 4;

    for (int k0 = 0; k0 < K; k0 += 8) {
        float4 a = *(const float4*)(Xb + (size_t)arow * K + k0 + acol);
        As[acol + 0][arow] = a.x;
        As[acol + 1][arow] = a.y;
        As[acol + 2][arow] = a.z;
        As[acol + 3][arow] = a.w;
        *(float4*)(&Bs[brow][bcol]) = *(const float4*)(W + (size_t)(k0 + brow) * CHID + bcol);
        __syncthreads();
#pragma unroll
        for (int kk = 0; kk < 8; kk++) {
            float ra[8], rb[8];
            *(float4*)(ra)     = *(const float4*)(&As[kk][ty * 8]);
            *(float4*)(ra + 4) = *(const float4*)(&As[kk][ty * 8 + 4]);
            *(float4*)(rb)     = *(const float4*)(&Bs[kk][tx * 8]);
            *(float4*)(rb + 4) = *(const float4*)(&Bs[kk][tx * 8 + 4]);
#pragma unroll
            for (int u = 0; u < 8; u++)
#pragma unroll
                for (int v = 0; v < 8; v++)
                    acc[u][v] = fmaf(ra[u], rb[v], acc[u][v]);
        }
        __syncthreads();
    }

#pragma unroll
    for (int u = 0; u < 8; u++) {
        int row = ty * 8 + u;
        size_t base = ((size_t)(b * NNODE + rt * 128 + row)) * CHID + tx * 8;
        __nv_bfloat16 hi8[8], lo8[8];
#pragma unroll
        for (int v = 0; v < 8; v++) {
            float val = acc[u][v];
            __nv_bfloat16 hi = __float2bfloat16(val);
            hi8[v] = hi;
            lo8[v] = __float2bfloat16(val - __bfloat162float(hi));
        }
        *(uint4*)(Hhi + base) = *(const uint4*)hi8;
        *(uint4*)(Hlo + base) = *(const uint4*)lo8;
    }
}

// ---------------- K4: mma.sync GCN GEMM: hout = silu(mask*(A@H + bias)) ----------------
__device__ __forceinline__ void load_chunk(uint32_t st, int c, int tid,
                                           const char* Ah, const char* Al,
                                           const char* Bh, const char* Bl) {
    // A: 128 rows x 64B (KC=32 bf16) = 512 x 16B items, 2 per thread
#pragma unroll
    for (int i = 0; i < 2; i++) {
        int item = tid + i * 256;
        int row = item >> 2, seg = item & 3;
        uint32_t so = (uint32_t)(row * ASTR + seg * 16);
        size_t   go = (size_t)row * (NNODE * 2) + (size_t)c * (KC * 2) + seg * 16;
        cp16(st + OFF_AHI + so, Ah + go);
        cp16(st + OFF_ALO + so, Al + go);
    }
    // H: 32 rows x 256B = 512 x 16B items, 2 per thread
#pragma unroll
    for (int i = 0; i < 2; i++) {
        int item = tid + i * 256;
        int kr = item >> 4, seg = item & 15;
        uint32_t so = (uint32_t)(kr * HSTR + seg * 16);
        size_t   go = (size_t)(c * KC + kr) * (CHID * 2) + seg * 16;
        cp16(st + OFF_HHI + so, Bh + go);
        cp16(st + OFF_HLO + so, Bl + go);
    }
    CP_COMMIT();
}

__global__ __launch_bounds__(256, 2)
void gcn_mma_kernel(const __nv_bfloat16* __restrict__ Ahi, const __nv_bfloat16* __restrict__ Alo,
                    const __nv_bfloat16* __restrict__ Hhi, const __nv_bfloat16* __restrict__ Hlo,
                    const float* __restrict__ bias, const int* __restrict__ mask,
                    float* __restrict__ Hout) {
    extern __shared__ char smem[];
    uint32_t sb = smem_u32(smem);
    int tid = threadIdx.x;
    int wid = tid >> 5, lane = tid & 31;
    int warpM = wid >> 2, warpN = wid & 3;

    int b = blockIdx.x >> 2, rt = blockIdx.x & 3;
    const char* Ah = (const char*)Ahi + ((size_t)(b * NNODE + rt * 128)) * (NNODE * 2);
    const char* Al = (const char*)Alo + ((size_t)(b * NNODE + rt * 128)) * (NNODE * 2);
    const char* Bh = (const char*)Hhi + ((size_t)b * NNODE) * (CHID * 2);
    const char* Bl = (const char*)Hlo + ((size_t)b * NNODE) * (CHID * 2);

    uint32_t aRow = (uint32_t)((warpM * 64 + (lane & 15)) * ASTR + (lane >> 4) * 16);
    uint32_t bRow = (uint32_t)(((lane & 7) + ((lane >> 3) & 1) * 8) * HSTR
                               + (warpN * 32 + ((lane >> 4) & 1) * 8) * 2);

    load_chunk(sb, 0, tid, Ah, Al, Bh, Bl);
    load_chunk(sb + STAGEB, 1, tid, Ah, Al, Bh, Bl);

    float acc[4][4][4];
#pragma unroll
    for (int m = 0; m < 4; m++)
#pragma unroll
        for (int n = 0; n < 4; n++)
#pragma unroll
            for (int k = 0; k < 4; k++) acc[m][n][k] = 0.f;

    for (int c = 0; c < NCHUNK; c++) {
        CP_WAIT1();
        __syncthreads();
        uint32_t st = sb + (uint32_t)(c & 1) * STAGEB;
#pragma unroll
        for (int ks = 0; ks < KC / 16; ks++) {
            uint32_t ahi[4][4], alo[4][4];
#pragma unroll
            for (int mt = 0; mt < 4; mt++) {
                uint32_t ad = st + aRow + (uint32_t)(mt * 16 * ASTR + ks * 32);
                ldm_x4(ahi[mt][0], ahi[mt][1], ahi[mt][2], ahi[mt][3], ad + OFF_AHI);
                ldm_x4(alo[mt][0], alo[mt][1], alo[mt][2], alo[mt][3], ad + OFF_ALO);
            }
            uint32_t bhi[2][4], blo[2][4];
#pragma unroll
            for (int ng = 0; ng < 2; ng++) {
                uint32_t bd = st + bRow + (uint32_t)(ks * 16 * HSTR + ng * 32);
                ldm_x4t(bhi[ng][0], bhi[ng][1], bhi[ng][2], bhi[ng][3], bd + OFF_HHI);
                ldm_x4t(blo[ng][0], blo[ng][1], blo[ng][2], blo[ng][3], bd + OFF_HLO);
            }
#pragma unroll
            for (int mt = 0; mt < 4; mt++)
#pragma unroll
                for (int nt = 0; nt < 4; nt++) {
                    int ng = nt >> 1, hf = nt & 1;
                    mma16816(acc[mt][nt], ahi[mt], bhi[ng][hf * 2], bhi[ng][hf * 2 + 1]);
                    mma16816(acc[mt][nt], ahi[mt], blo[ng][hf * 2], blo[ng][hf * 2 + 1]);
                    mma16816(acc[mt][nt], alo[mt], bhi[ng][hf * 2], bhi[ng][hf * 2 + 1]);
                }
        }
        __syncthreads();
        if (c + 2 < NCHUNK)
            load_chunk(sb + (uint32_t)(c & 1) * STAGEB, c + 2, tid, Ah, Al, Bh, Bl);
        else
            CP_COMMIT();   // keep wait_group accounting constant
    }

    // epilogue: bias + mask + silu -> fp32
    int rowBase = b * NNODE + rt * 128 + warpM * 64;
    float* Ob = Hout + (size_t)rowBase * CHID;
#pragma unroll
    for (int mt = 0; mt < 4; mt++) {
        int r0 = mt * 16 + (lane >> 2);
        float m0 = (float)mask[rowBase + r0];
        float m1 = (float)mask[rowBase + r0 + 8];
#pragma unroll
        for (int nt = 0; nt < 4; nt++) {
            int col = warpN * 32 + nt * 8 + (lane & 3) * 2;
            float b0v = bias[col], b1v = bias[col + 1];
            float z0 = (acc[mt][nt][0] + b0v) * m0;
            float z1 = (acc[mt][nt][1] + b1v) * m0;
            float z2 = (acc[mt][nt][2] + b0v) * m1;
            float z3 = (acc[mt][nt][3] + b1v) * m1;
            float2 o0 = make_float2(z0 / (1.f + __expf(-z0)), z1 / (1.f + __expf(-z1)));
            float2 o1 = make_float2(z2 / (1.f + __expf(-z2)), z3 / (1.f + __expf(-z3)));
            *(float2*)(Ob + (size_t)r0 * CHID + col)       = o0;
            *(float2*)(Ob + (size_t)(r0 + 8) * CHID + col) = o1;
        }
    }
}

// ---------------- K5: mean pool + MLP head ----------------
__global__ void head_kernel(const float* __restrict__ hfinal,
                            const float* __restrict__ Wl1, const float* __restrict__ bl1,
                            const float* __restrict__ Wl2, const float* __restrict__ bl2,
                            float* __restrict__ out) {
    int b = blockIdx.x;
    int c = threadIdx.x;     // 128
    int w = threadIdx.y;     // 4
    const float* base = hfinal + (size_t)b * NNODE * CHID;
    float s = 0.f;
    for (int i = w; i < NNODE; i += 4) s += base[(size_t)i * CHID + c];
    __shared__ float red[4][CHID];
    red[w][c] = s;
    __syncthreads();
    __shared__ float g[CHID], g1[CHID];
    if (w == 0) {
        g[c] = (red[0][c] + red[1][c] + red[2][c] + red[3][c]) * (1.0f / NNODE);
    }
    __syncthreads();
    if (w == 0) {
        float acc = bl1[c];
        for (int k = 0; k < CHID; k++) acc = fmaf(g[k], Wl1[k * CHID + c], acc);
        g1[c] = acc / (1.f + __expf(-acc));
    }
    __syncthreads();
    if (w == 0 && c < COUT) {
        float acc2 = bl2[c];
        for (int k = 0; k < CHID; k++) acc2 = fmaf(g1[k], Wl2[k * COUT + c], acc2);
        out[b * COUT + c] = acc2;
    }
}

// ---------------- launch ----------------
extern "C" void kernel_launch(void* const* d_in, const int* in_sizes, int n_in,
                              void* d_out, int out_size) {
    const float* x    = (const float*)d_in[0];
    const float* adj  = (const float*)d_in[1];
    const int*   mask = (const int*)  d_in[2];
    const float* W0   = (const float*)d_in[3];
    const float* b0   = (const float*)d_in[4];
    const float* W1   = (const float*)d_in[5];
    const float* b1   = (const float*)d_in[6];
    const float* Wl1  = (const float*)d_in[7];
    const float* bl1  = (const float*)d_in[8];
    const float* Wl2  = (const float*)d_in[9];
    const float* bl2  = (const float*)d_in[10];
    float* out = (float*)d_out;

    __nv_bfloat16 *dAhi, *dAlo, *dHhi, *dHlo;
    float *dHout;
    cudaGetSymbolAddress((void**)&dAhi, g_Ahi);
    cudaGetSymbolAddress((void**)&dAlo, g_Alo);
    cudaGetSymbolAddress((void**)&dHhi, g_Hhi);
    cudaGetSymbolAddress((void**)&dHlo, g_Hlo);
    cudaGetSymbolAddress((void**)&dHout, g_hout);

    static int smem_set = 0;
    if (!smem_set) {
        cudaFuncSetAttribute(gcn_mma_kernel, cudaFuncAttributeMaxDynamicSharedMemorySize, SMEM_DYN);
        smem_set = 1;
    }

    // 1) degrees
    deg_kernel<<<BATCH * NNODE, 128>>>(adj);
    // 2) collapsed normalized adjacency (bf16 hi/lo)
    buildA_kernel<<<(BATCH * NNODE * NNODE) / (256 * 4), 256>>>(adj);
    // 3) H = x @ W0 (split bf16)
    lin_kernel<<<BATCH * 4, 256>>>(x, W0, CIN, dHhi, dHlo);
    // 4) layer 1 (tensor cores via mma.sync)
    gcn_mma_kernel<<<BATCH * 4, 256, SMEM_DYN>>>(dAhi, dAlo, dHhi, dHlo, b0, mask, dHout);
    // 5) H = h1 @ W1 (split bf16)
    lin_kernel<<<BATCH * 4, 256>>>(dHout, W1, CHID, dHhi, dHlo);
    // 6) layer 2
    gcn_mma_kernel<<<BATCH * 4, 256, SMEM_DYN>>>(dAhi, dAlo, dHhi, dHlo, b1, mask, dHout);
    // 7) mean pool + MLP head
    head_kernel<<<BATCH, dim3(CHID, 4)>>>(dHout, Wl1, bl1, Wl2, bl2, out);
}

// round 7
// speedup vs baseline: 1.8834x; 1.0222x over previous
#include <cuda_runtime.h>
#include <cuda_bf16.h>
#include <cstdint>
#include <math.h>

#define BATCH 64
#define NNODE 512
#define NEDGE 4
#define CIN   64
#define CHID  128
#define COUT  16

// ---- mma.sync GEMM tiling ----
#define KC 32                               // K per pipeline chunk
#define NCHUNK (NNODE / KC)                 // 16
#define NSTG 3                              // pipeline stages
#define ASTR 80                             // A smem row stride bytes (32 bf16 + 16 pad)
#define HSTR 272                            // H smem row stride bytes (128 bf16 + 8 pad)
#define OFF_AHI 0
#define OFF_ALO (128 * ASTR)                // 10240
#define OFF_HHI (2 * 128 * ASTR)            // 20480
#define OFF_HLO (2 * 128 * ASTR + KC * HSTR)
#define STAGEB  (2 * 128 * ASTR + 2 * KC * HSTR)   // 37888
#define SMEM_DYN (NSTG * STAGEB)                    // 113664 -> 2 CTAs/SM

// ---------------- device scratch ----------------
__device__ float          g_deg [BATCH * NNODE * NEDGE];
__device__ __nv_bfloat16  g_Ahi [(size_t)BATCH * NNODE * NNODE];   // 32MB
__device__ __nv_bfloat16  g_Alo [(size_t)BATCH * NNODE * NNODE];   // 32MB
__device__ __nv_bfloat16  g_Hhi [(size_t)BATCH * NNODE * CHID];    // 8MB  [b][k][n]
__device__ __nv_bfloat16  g_Hlo [(size_t)BATCH * NNODE * CHID];    // 8MB
__device__ float          g_hout[(size_t)BATCH * NNODE * CHID];    // 16MB (layer-1 only)
__device__ float          g_part[BATCH * 4 * CHID];                // pooled partials

// ---------------- PTX helpers ----------------
__device__ __forceinline__ uint32_t smem_u32(const void* p) {
    uint32_t a;
    asm("{ .reg .u64 t; cvta.to.shared.u64 t, %1; cvt.u32.u64 %0, t; }" : "=r"(a) : "l"(p));
    return a;
}
__device__ __forceinline__ void cp16(uint32_t dst, const void* src) {
    asm volatile("cp.async.cg.shared.global [%0], [%1], 16;" :: "r"(dst), "l"(src));
}
#define CP_COMMIT() asm volatile("cp.async.commit_group;" ::: "memory")
#define CP_WAIT1()  asm volatile("cp.async.wait_group 1;"  ::: "memory")

__device__ __forceinline__ void ldm_x4(uint32_t& r0, uint32_t& r1, uint32_t& r2, uint32_t& r3,
                                       uint32_t a) {
    asm volatile("ldmatrix.sync.aligned.m8n8.x4.shared.b16 {%0,%1,%2,%3}, [%4];"
                 : "=r"(r0), "=r"(r1), "=r"(r2), "=r"(r3) : "r"(a));
}
__device__ __forceinline__ void ldm_x4t(uint32_t& r0, uint32_t& r1, uint32_t& r2, uint32_t& r3,
                                        uint32_t a) {
    asm volatile("ldmatrix.sync.aligned.m8n8.x4.trans.shared.b16 {%0,%1,%2,%3}, [%4];"
                 : "=r"(r0), "=r"(r1), "=r"(r2), "=r"(r3) : "r"(a));
}
__device__ __forceinline__ void mma16816(float* c, const uint32_t* a, uint32_t b0, uint32_t b1) {
    asm volatile(
        "mma.sync.aligned.m16n8k16.row.col.f32.bf16.bf16.f32 "
        "{%0,%1,%2,%3}, {%4,%5,%6,%7}, {%8,%9}, {%0,%1,%2,%3};"
        : "+f"(c[0]), "+f"(c[1]), "+f"(c[2]), "+f"(c[3])
        : "r"(a[0]), "r"(a[1]), "r"(a[2]), "r"(a[3]), "r"(b0), "r"(b1));
}

// ---------------- K1: degrees -> rsqrt(max(sum,1)), MLP=4 ----------------
__global__ void deg_kernel(const float* __restrict__ adj) {
    int bi = blockIdx.x;
    int i  = bi & (NNODE - 1);
    const float4* row = (const float4*)(adj + (size_t)bi * (NNODE * NEDGE));
    int j = threadIdx.x;
    float4 v0 = row[j];
    float4 v1 = row[j + 128];
    float4 v2 = row[j + 256];
    float4 v3 = row[j + 384];
    if (j == i)         v0 = make_float4(1.f, 1.f, 1.f, 1.f);
    if (j + 128 == i)   v1 = make_float4(1.f, 1.f, 1.f, 1.f);
    if (j + 256 == i)   v2 = make_float4(1.f, 1.f, 1.f, 1.f);
    if (j + 384 == i)   v3 = make_float4(1.f, 1.f, 1.f, 1.f);
    float4 s;
    s.x = (v0.x + v1.x) + (v2.x + v3.x);
    s.y = (v0.y + v1.y) + (v2.y + v3.y);
    s.z = (v0.z + v1.z) + (v2.z + v3.z);
    s.w = (v0.w + v1.w) + (v2.w + v3.w);
    for (int o = 16; o > 0; o >>= 1) {
        s.x += __shfl_down_sync(0xffffffffu, s.x, o);
        s.y += __shfl_down_sync(0xffffffffu, s.y, o);
        s.z += __shfl_down_sync(0xffffffffu, s.z, o);
        s.w += __shfl_down_sync(0xffffffffu, s.w, o);
    }
    __shared__ float4 sh[4];
    int lane = threadIdx.x & 31, w = threadIdx.x >> 5;
    if (lane == 0) sh[w] = s;
    __syncthreads();
    if (threadIdx.x == 0) {
        float4 t = sh[0];
        t.x += sh[1].x + sh[2].x + sh[3].x;
        t.y += sh[1].y + sh[2].y + sh[3].y;
        t.z += sh[1].z + sh[2].z + sh[3].z;
        t.w += sh[1].w + sh[2].w + sh[3].w;
        float4 r;
        r.x = rsqrtf(fmaxf(t.x, 1.f));
        r.y = rsqrtf(fmaxf(t.y, 1.f));
        r.z = rsqrtf(fmaxf(t.z, 1.f));
        r.w = rsqrtf(fmaxf(t.w, 1.f));
        ((float4*)g_deg)[bi] = r;
    }
}

// ---------------- K2: collapsed adjacency -> bf16 hi/lo, 4 elems/thread ----------------
__global__ void buildA_kernel(const float* __restrict__ adj) {
    size_t blk = (size_t)(gridDim.x - 1 - blockIdx.x);
    size_t t0 = (blk * blockDim.x + threadIdx.x) * 4;
    int j = (int)(t0 & (NNODE - 1));
    int i = (int)((t0 >> 9) & (NNODE - 1));
    int b = (int)(t0 >> 18);
    const float4* ap = (const float4*)adj + t0;
    float4 di = ((const float4*)g_deg)[b * NNODE + i];
    const float4* djp = ((const float4*)g_deg) + b * NNODE + j;
    __nv_bfloat16 hi4[4], lo4[4];
#pragma unroll
    for (int e = 0; e < 4; e++) {
        float4 a = ap[e];
        if (j + e == i) a = make_float4(1.f, 1.f, 1.f, 1.f);
        float4 dj = djp[e];
        float v = a.x * di.x * dj.x + a.y * di.y * dj.y + a.z * di.z * dj.z + a.w * di.w * dj.w;
        __nv_bfloat16 hi = __float2bfloat16(v);
        hi4[e] = hi;
        lo4[e] = __float2bfloat16(v - __bfloat162float(hi));
    }
    *(uint2*)(g_Ahi + t0) = *(const uint2*)hi4;
    *(uint2*)(g_Alo + t0) = *(const uint2*)lo4;
}

// ---------------- K3: lin: H[b][k][n] (hi/lo bf16) = X @ W ----------------
__global__ __launch_bounds__(256)
void lin_kernel(const float* __restrict__ X, const float* __restrict__ W, int K,
                __nv_bfloat16* __restrict__ Hhi, __nv_bfloat16* __restrict__ Hlo) {
    int b  = blockIdx.x >> 2;
    int rt = blockIdx.x & 3;
    const float* Xb = X + (size_t)(b * NNODE + rt * 128) * K;

    __shared__ float As[8][128];
    __shared__ float Bs[8][128];

    int tid = threadIdx.x;
    int tx = tid & 15, ty = tid >> 4;

    float acc[8][8];
#pragma unroll
    for (int u = 0; u < 8; u++)
#pragma unroll
        for (int v = 0; v < 8; v++) acc[u][v] = 0.f;

    int arow = tid >> 1, acol = (tid & 1) * 4;
    int brow = tid >> 5, bcol = (tid & 31) * 4;

    for (int k0 = 0; k0 < K; k0 += 8) {
        float4 a = *(const float4*)(Xb + (size_t)arow * K + k0 + acol);
        As[acol + 0][arow] = a.x;
        As[acol + 1][arow] = a.y;
        As[acol + 2][arow] = a.z;
        As[acol + 3][arow] = a.w;
        *(float4*)(&Bs[brow][bcol]) = *(const float4*)(W + (size_t)(k0 + brow) * CHID + bcol);
        __syncthreads();
#pragma unroll
        for (int kk = 0; kk < 8; kk++) {
            float ra[8], rb[8];
            *(float4*)(ra)     = *(const float4*)(&As[kk][ty * 8]);
            *(float4*)(ra + 4) = *(const float4*)(&As[kk][ty * 8 + 4]);
            *(float4*)(rb)     = *(const float4*)(&Bs[kk][tx * 8]);
            *(float4*)(rb + 4) = *(const float4*)(&Bs[kk][tx * 8 + 4]);
#pragma unroll
            for (int u = 0; u < 8; u++)
#pragma unroll
                for (int v = 0; v < 8; v++)
                    acc[u][v] = fmaf(ra[u], rb[v], acc[u][v]);
        }
        __syncthreads();
    }

#pragma unroll
    for (int u = 0; u < 8; u++) {
        int row = ty * 8 + u;
        size_t base = ((size_t)(b * NNODE + rt * 128 + row)) * CHID + tx * 8;
        __nv_bfloat16 hi8[8], lo8[8];
#pragma unroll
        for (int v = 0; v < 8; v++) {
            float val = acc[u][v];
            __nv_bfloat16 hi = __float2bfloat16(val);
            hi8[v] = hi;
            lo8[v] = __float2bfloat16(val - __bfloat162float(hi));
        }
        *(uint4*)(Hhi + base) = *(const uint4*)hi8;
        *(uint4*)(Hlo + base) = *(const uint4*)lo8;
    }
}

// ---------------- K4: mma.sync GCN GEMM (3-stage pipeline) ----------------
__device__ __forceinline__ void load_chunk(uint32_t st, int c, int tid,
                                           const char* Ah, const char* Al,
                                           const char* Bh, const char* Bl) {
#pragma unroll
    for (int i = 0; i < 2; i++) {
        int item = tid + i * 256;
        int row = item >> 2, seg = item & 3;
        uint32_t so = (uint32_t)(row * ASTR + seg * 16);
        size_t   go = (size_t)row * (NNODE * 2) + (size_t)c * (KC * 2) + seg * 16;
        cp16(st + OFF_AHI + so, Ah + go);
        cp16(st + OFF_ALO + so, Al + go);
    }
#pragma unroll
    for (int i = 0; i < 2; i++) {
        int item = tid + i * 256;
        int kr = item >> 4, seg = item & 15;
        uint32_t so = (uint32_t)(kr * HSTR + seg * 16);
        size_t   go = (size_t)(c * KC + kr) * (CHID * 2) + seg * 16;
        cp16(st + OFF_HHI + so, Bh + go);
        cp16(st + OFF_HLO + so, Bl + go);
    }
    CP_COMMIT();
}

template<bool POOL>
__global__ __launch_bounds__(256, 2)
void gcn_mma_kernel(const __nv_bfloat16* __restrict__ Ahi, const __nv_bfloat16* __restrict__ Alo,
                    const __nv_bfloat16* __restrict__ Hhi, const __nv_bfloat16* __restrict__ Hlo,
                    const float* __restrict__ bias, const int* __restrict__ mask,
                    float* __restrict__ Hout, float* __restrict__ part) {
    extern __shared__ char smem[];
    uint32_t sb = smem_u32(smem);
    int tid = threadIdx.x;
    int wid = tid >> 5, lane = tid & 31;
    int warpM = wid >> 2, warpN = wid & 3;

    int b = blockIdx.x >> 2, rt = blockIdx.x & 3;
    const char* Ah = (const char*)Ahi + ((size_t)(b * NNODE + rt * 128)) * (NNODE * 2);
    const char* Al = (const char*)Alo + ((size_t)(b * NNODE + rt * 128)) * (NNODE * 2);
    const char* Bh = (const char*)Hhi + ((size_t)b * NNODE) * (CHID * 2);
    const char* Bl = (const char*)Hlo + ((size_t)b * NNODE) * (CHID * 2);

    uint32_t aRow = (uint32_t)((warpM * 64 + (lane & 15)) * ASTR + (lane >> 4) * 16);
    uint32_t bRow = (uint32_t)(((lane & 7) + ((lane >> 3) & 1) * 8) * HSTR
                               + (warpN * 32 + ((lane >> 4) & 1) * 8) * 2);

    load_chunk(sb, 0, tid, Ah, Al, Bh, Bl);
    load_chunk(sb + STAGEB, 1, tid, Ah, Al, Bh, Bl);

    float acc[4][4][4];
#pragma unroll
    for (int m = 0; m < 4; m++)
#pragma unroll
        for (int n = 0; n < 4; n++)
#pragma unroll
            for (int k = 0; k < 4; k++) acc[m][n][k] = 0.f;

    int stg = 0;       // stage of chunk c
    for (int c = 0; c < NCHUNK; c++) {
        CP_WAIT1();            // chunk c landed (c+1 may still be in flight)
        __syncthreads();       // all warps past chunk c-1 compute; stage (c+2)%3 reusable
        int pstg = stg + 2; if (pstg >= NSTG) pstg -= NSTG;
        if (c + 2 < NCHUNK)
            load_chunk(sb + (uint32_t)pstg * STAGEB, c + 2, tid, Ah, Al, Bh, Bl);
        else
            CP_COMMIT();       // keep wait_group accounting constant
        uint32_t st = sb + (uint32_t)stg * STAGEB;
#pragma unroll
        for (int ks = 0; ks < KC / 16; ks++) {
            uint32_t ahi[4][4], alo[4][4];
#pragma unroll
            for (int mt = 0; mt < 4; mt++) {
                uint32_t ad = st + aRow + (uint32_t)(mt * 16 * ASTR + ks * 32);
                ldm_x4(ahi[mt][0], ahi[mt][1], ahi[mt][2], ahi[mt][3], ad + OFF_AHI);
                ldm_x4(alo[mt][0], alo[mt][1], alo[mt][2], alo[mt][3], ad + OFF_ALO);
            }
            uint32_t bhi[2][4], blo[2][4];
#pragma unroll
            for (int ng = 0; ng < 2; ng++) {
                uint32_t bd = st + bRow + (uint32_t)(ks * 16 * HSTR + ng * 32);
                ldm_x4t(bhi[ng][0], bhi[ng][1], bhi[ng][2], bhi[ng][3], bd + OFF_HHI);
                ldm_x4t(blo[ng][0], blo[ng][1], blo[ng][2], blo[ng][3], bd + OFF_HLO);
            }
#pragma unroll
            for (int mt = 0; mt < 4; mt++)
#pragma unroll
                for (int nt = 0; nt < 4; nt++) {
                    int ng = nt >> 1, hf = nt & 1;
                    mma16816(acc[mt][nt], ahi[mt], bhi[ng][hf * 2], bhi[ng][hf * 2 + 1]);
                    mma16816(acc[mt][nt], ahi[mt], blo[ng][hf * 2], blo[ng][hf * 2 + 1]);
                    mma16816(acc[mt][nt], alo[mt], bhi[ng][hf * 2], bhi[ng][hf * 2 + 1]);
                }
        }
        if (++stg >= NSTG) stg = 0;
    }

    // epilogue: bias + mask + silu
    int rowBase = b * NNODE + rt * 128 + warpM * 64;
    float* Ob = Hout + (size_t)rowBase * CHID;
    float csum[8];
#pragma unroll
    for (int k = 0; k < 8; k++) csum[k] = 0.f;

#pragma unroll
    for (int mt = 0; mt < 4; mt++) {
        int r0 = mt * 16 + (lane >> 2);
        float m0 = (float)mask[rowBase + r0];
        float m1 = (float)mask[rowBase + r0 + 8];
#pragma unroll
        for (int nt = 0; nt < 4; nt++) {
            int col = warpN * 32 + nt * 8 + (lane & 3) * 2;
            float b0v = bias[col], b1v = bias[col + 1];
            float z0 = (acc[mt][nt][0] + b0v) * m0;
            float z1 = (acc[mt][nt][1] + b1v) * m0;
            float z2 = (acc[mt][nt][2] + b0v) * m1;
            float z3 = (acc[mt][nt][3] + b1v) * m1;
            float o0 = z0 / (1.f + __expf(-z0));
            float o1 = z1 / (1.f + __expf(-z1));
            float o2 = z2 / (1.f + __expf(-z2));
            float o3 = z3 / (1.f + __expf(-z3));
            if (POOL) {
                csum[nt * 2]     += o0 + o2;
                csum[nt * 2 + 1] += o1 + o3;
            } else {
                *(float2*)(Ob + (size_t)r0 * CHID + col)       = make_float2(o0, o1);
                *(float2*)(Ob + (size_t)(r0 + 8) * CHID + col) = make_float2(o2, o3);
            }
        }
    }

    if (POOL) {
        __shared__ float spool[2][CHID];
#pragma unroll
        for (int off = 4; off < 32; off <<= 1)
#pragma unroll
            for (int k = 0; k < 8; k++)
                csum[k] += __shfl_xor_sync(0xffffffffu, csum[k], off);
        if ((lane >> 2) == 0) {
#pragma unroll
            for (int nt = 0; nt < 4; nt++) {
                int col = warpN * 32 + nt * 8 + (lane & 3) * 2;
                spool[warpM][col]     = csum[nt * 2];
                spool[warpM][col + 1] = csum[nt * 2 + 1];
            }
        }
        __syncthreads();
        if (tid < CHID)
            part[(b * 4 + rt) * CHID + tid] = spool[0][tid] + spool[1][tid];
    }
}

// ---------------- K5: head from pooled partials ----------------
__global__ void head_kernel(const float* __restrict__ part,
                            const float* __restrict__ Wl1, const float* __restrict__ bl1,
                            const float* __restrict__ Wl2, const float* __restrict__ bl2,
                            float* __restrict__ out) {
    int b = blockIdx.x;
    int c = threadIdx.x;     // 128 threads
    __shared__ float g[CHID], g1[CHID];
    const float* pb = part + b * 4 * CHID;
    g[c] = (pb[c] + pb[CHID + c] + pb[2 * CHID + c] + pb[3 * CHID + c]) * (1.0f / NNODE);
    __syncthreads();
    float acc = bl1[c];
    for (int k = 0; k < CHID; k++) acc = fmaf(g[k], Wl1[k * CHID + c], acc);
    g1[c] = acc / (1.f + __expf(-acc));
    __syncthreads();
    if (c < COUT) {
        float acc2 = bl2[c];
        for (int k = 0; k < CHID; k++) acc2 = fmaf(g1[k], Wl2[k * COUT + c], acc2);
        out[b * COUT + c] = acc2;
    }
}

// ---------------- launch ----------------
extern "C" void kernel_launch(void* const* d_in, const int* in_sizes, int n_in,
                              void* d_out, int out_size) {
    const float* x    = (const float*)d_in[0];
    const float* adj  = (const float*)d_in[1];
    const int*   mask = (const int*)  d_in[2];
    const float* W0   = (const float*)d_in[3];
    const float* b0   = (const float*)d_in[4];
    const float* W1   = (const float*)d_in[5];
    const float* b1   = (const float*)d_in[6];
    const float* Wl1  = (const float*)d_in[7];
    const float* bl1  = (const float*)d_in[8];
    const float* Wl2  = (const float*)d_in[9];
    const float* bl2  = (const float*)d_in[10];
    float* out = (float*)d_out;

    __nv_bfloat16 *dAhi, *dAlo, *dHhi, *dHlo;
    float *dHout, *dPart;
    cudaGetSymbolAddress((void**)&dAhi, g_Ahi);
    cudaGetSymbolAddress((void**)&dAlo, g_Alo);
    cudaGetSymbolAddress((void**)&dHhi, g_Hhi);
    cudaGetSymbolAddress((void**)&dHlo, g_Hlo);
    cudaGetSymbolAddress((void**)&dHout, g_hout);
    cudaGetSymbolAddress((void**)&dPart, g_part);

    static int smem_set = 0;
    if (!smem_set) {
        cudaFuncSetAttribute(gcn_mma_kernel<false>,
                             cudaFuncAttributeMaxDynamicSharedMemorySize, SMEM_DYN);
        cudaFuncSetAttribute(gcn_mma_kernel<true>,
                             cudaFuncAttributeMaxDynamicSharedMemorySize, SMEM_DYN);
        smem_set = 1;
    }

    // 1) degrees
    deg_kernel<<<BATCH * NNODE, 128>>>(adj);
    // 2) collapsed normalized adjacency (bf16 hi/lo)
    buildA_kernel<<<(BATCH * NNODE * NNODE) / (256 * 4), 256>>>(adj);
    // 3) H = x @ W0 (split bf16)
    lin_kernel<<<BATCH * 4, 256>>>(x, W0, CIN, dHhi, dHlo);
    // 4) layer 1 (writes h1 fp32)
    gcn_mma_kernel<false><<<BATCH * 4, 256, SMEM_DYN>>>(dAhi, dAlo, dHhi, dHlo, b0, mask,
                                                        dHout, dPart);
    // 5) H = h1 @ W1 (split bf16)
    lin_kernel<<<BATCH * 4, 256>>>(dHout, W1, CHID, dHhi, dHlo);
    // 6) layer 2 (fused mean-pool epilogue, no 16MB write)
    gcn_mma_kernel<true><<<BATCH * 4, 256, SMEM_DYN>>>(dAhi, dAlo, dHhi, dHlo, b1, mask,
                                                       dHout, dPart);
    // 7) MLP head from pooled partials
    head_kernel<<<BATCH, CHID>>>(dPart, Wl1, bl1, Wl2, bl2, out);
}

// round 8
// speedup vs baseline: 1.8867x; 1.0017x over previous
#include <cuda_runtime.h>
#include <cuda_bf16.h>
#include <cstdint>
#include <math.h>

#define BATCH 64
#define NNODE 512
#define NEDGE 4
#define CIN   64
#define CHID  128
#define COUT  16

// ---- mma.sync GEMM tiling ----
#define KC 32                               // K per pipeline chunk
#define NCHUNK (NNODE / KC)                 // 16
#define NSTG 3                              // pipeline stages
#define ASTR 80                             // A smem row stride bytes (32 bf16 + 16 pad)
#define HSTR 272                            // H smem row stride bytes (128 bf16 + 8 pad)
#define OFF_AHI 0
#define OFF_ALO (128 * ASTR)                // 10240
#define OFF_HHI (2 * 128 * ASTR)            // 20480
#define OFF_HLO (2 * 128 * ASTR + KC * HSTR)
#define STAGEB  (2 * 128 * ASTR + 2 * KC * HSTR)   // 37888
#define SMEM_DYN (NSTG * STAGEB)                    // 113664 -> 2 CTAs/SM

// ---------------- device scratch ----------------
__device__ float          g_deg [BATCH * NNODE * NEDGE];
__device__ __nv_bfloat16  g_Ahi [(size_t)BATCH * NNODE * NNODE];   // 32MB
__device__ __nv_bfloat16  g_Alo [(size_t)BATCH * NNODE * NNODE];   // 32MB
__device__ __nv_bfloat16  g_Hhi [(size_t)BATCH * NNODE * CHID];    // 8MB  [b][k][n]
__device__ __nv_bfloat16  g_Hlo [(size_t)BATCH * NNODE * CHID];    // 8MB
__device__ float          g_hout[(size_t)BATCH * NNODE * CHID];    // 16MB (layer-1 only)
__device__ float          g_part[BATCH * 4 * CHID];                // pooled partials

// ---------------- PTX helpers ----------------
__device__ __forceinline__ uint32_t smem_u32(const void* p) {
    uint32_t a;
    asm("{ .reg .u64 t; cvta.to.shared.u64 t, %1; cvt.u32.u64 %0, t; }" : "=r"(a) : "l"(p));
    return a;
}
__device__ __forceinline__ void cp16(uint32_t dst, const void* src) {
    asm volatile("cp.async.cg.shared.global [%0], [%1], 16;" :: "r"(dst), "l"(src));
}
#define CP_COMMIT() asm volatile("cp.async.commit_group;" ::: "memory")
#define CP_WAIT1()  asm volatile("cp.async.wait_group 1;"  ::: "memory")

__device__ __forceinline__ void ldm_x4(uint32_t& r0, uint32_t& r1, uint32_t& r2, uint32_t& r3,
                                       uint32_t a) {
    asm volatile("ldmatrix.sync.aligned.m8n8.x4.shared.b16 {%0,%1,%2,%3}, [%4];"
                 : "=r"(r0), "=r"(r1), "=r"(r2), "=r"(r3) : "r"(a));
}
__device__ __forceinline__ void ldm_x4t(uint32_t& r0, uint32_t& r1, uint32_t& r2, uint32_t& r3,
                                        uint32_t a) {
    asm volatile("ldmatrix.sync.aligned.m8n8.x4.trans.shared.b16 {%0,%1,%2,%3}, [%4];"
                 : "=r"(r0), "=r"(r1), "=r"(r2), "=r"(r3) : "r"(a));
}
__device__ __forceinline__ void mma16816(float* c, const uint32_t* a, uint32_t b0, uint32_t b1) {
    asm volatile(
        "mma.sync.aligned.m16n8k16.row.col.f32.bf16.bf16.f32 "
        "{%0,%1,%2,%3}, {%4,%5,%6,%7}, {%8,%9}, {%0,%1,%2,%3};"
        : "+f"(c[0]), "+f"(c[1]), "+f"(c[2]), "+f"(c[3])
        : "r"(a[0]), "r"(a[1]), "r"(a[2]), "r"(a[3]), "r"(b0), "r"(b1));
}

// ---------------- K1: degrees -> rsqrt(max(sum,1)), MLP=4 ----------------
__global__ void deg_kernel(const float* __restrict__ adj) {
    int bi = blockIdx.x;
    int i  = bi & (NNODE - 1);
    const float4* row = (const float4*)(adj + (size_t)bi * (NNODE * NEDGE));
    int j = threadIdx.x;
    float4 v0 = row[j];
    float4 v1 = row[j + 128];
    float4 v2 = row[j + 256];
    float4 v3 = row[j + 384];
    if (j == i)         v0 = make_float4(1.f, 1.f, 1.f, 1.f);
    if (j + 128 == i)   v1 = make_float4(1.f, 1.f, 1.f, 1.f);
    if (j + 256 == i)   v2 = make_float4(1.f, 1.f, 1.f, 1.f);
    if (j + 384 == i)   v3 = make_float4(1.f, 1.f, 1.f, 1.f);
    float4 s;
    s.x = (v0.x + v1.x) + (v2.x + v3.x);
    s.y = (v0.y + v1.y) + (v2.y + v3.y);
    s.z = (v0.z + v1.z) + (v2.z + v3.z);
    s.w = (v0.w + v1.w) + (v2.w + v3.w);
    for (int o = 16; o > 0; o >>= 1) {
        s.x += __shfl_down_sync(0xffffffffu, s.x, o);
        s.y += __shfl_down_sync(0xffffffffu, s.y, o);
        s.z += __shfl_down_sync(0xffffffffu, s.z, o);
        s.w += __shfl_down_sync(0xffffffffu, s.w, o);
    }
    __shared__ float4 sh[4];
    int lane = threadIdx.x & 31, w = threadIdx.x >> 5;
    if (lane == 0) sh[w] = s;
    __syncthreads();
    if (threadIdx.x == 0) {
        float4 t = sh[0];
        t.x += sh[1].x + sh[2].x + sh[3].x;
        t.y += sh[1].y + sh[2].y + sh[3].y;
        t.z += sh[1].z + sh[2].z + sh[3].z;
        t.w += sh[1].w + sh[2].w + sh[3].w;
        float4 r;
        r.x = rsqrtf(fmaxf(t.x, 1.f));
        r.y = rsqrtf(fmaxf(t.y, 1.f));
        r.z = rsqrtf(fmaxf(t.z, 1.f));
        r.w = rsqrtf(fmaxf(t.w, 1.f));
        ((float4*)g_deg)[bi] = r;
    }
}

// ---------------- K2: collapsed adjacency -> bf16 hi/lo, 4 elems/thread ----------------
__global__ void buildA_kernel(const float* __restrict__ adj) {
    size_t blk = (size_t)(gridDim.x - 1 - blockIdx.x);
    size_t t0 = (blk * blockDim.x + threadIdx.x) * 4;
    int j = (int)(t0 & (NNODE - 1));
    int i = (int)((t0 >> 9) & (NNODE - 1));
    int b = (int)(t0 >> 18);
    const float4* ap = (const float4*)adj + t0;
    float4 di = ((const float4*)g_deg)[b * NNODE + i];
    const float4* djp = ((const float4*)g_deg) + b * NNODE + j;
    __nv_bfloat16 hi4[4], lo4[4];
#pragma unroll
    for (int e = 0; e < 4; e++) {
        float4 a = ap[e];
        if (j + e == i) a = make_float4(1.f, 1.f, 1.f, 1.f);
        float4 dj = djp[e];
        float v = a.x * di.x * dj.x + a.y * di.y * dj.y + a.z * di.z * dj.z + a.w * di.w * dj.w;
        __nv_bfloat16 hi = __float2bfloat16(v);
        hi4[e] = hi;
        lo4[e] = __float2bfloat16(v - __bfloat162float(hi));
    }
    *(uint2*)(g_Ahi + t0) = *(const uint2*)hi4;
    *(uint2*)(g_Alo + t0) = *(const uint2*)lo4;
}

// ---------------- K3: lin: H[b][k][n] (hi/lo bf16) = X @ W ----------------
__global__ __launch_bounds__(256)
void lin_kernel(const float* __restrict__ X, const float* __restrict__ W, int K,
                __nv_bfloat16* __restrict__ Hhi, __nv_bfloat16* __restrict__ Hlo) {
    int b  = blockIdx.x >> 2;
    int rt = blockIdx.x & 3;
    const float* Xb = X + (size_t)(b * NNODE + rt * 128) * K;

    __shared__ float As[8][128];
    __shared__ float Bs[8][128];

    int tid = threadIdx.x;
    int tx = tid & 15, ty = tid >> 4;

    float acc[8][8];
#pragma unroll
    for (int u = 0; u < 8; u++)
#pragma unroll
        for (int v = 0; v < 8; v++) acc[u][v] = 0.f;

    int arow = tid >> 1, acol = (tid & 1) * 4;
    int brow = tid >> 5, bcol = (tid & 31) * 4;

    for (int k0 = 0; k0 < K; k0 += 8) {
        float4 a = *(const float4*)(Xb + (size_t)arow * K + k0 + acol);
        As[acol + 0][arow] = a.x;
        As[acol + 1][arow] = a.y;
        As[acol + 2][arow] = a.z;
        As[acol + 3][arow] = a.w;
        *(float4*)(&Bs[brow][bcol]) = *(const float4*)(W + (size_t)(k0 + brow) * CHID + bcol);
        __syncthreads();
#pragma unroll
        for (int kk = 0; kk < 8; kk++) {
            float ra[8], rb[8];
            *(float4*)(ra)     = *(const float4*)(&As[kk][ty * 8]);
            *(float4*)(ra + 4) = *(const float4*)(&As[kk][ty * 8 + 4]);
            *(float4*)(rb)     = *(const float4*)(&Bs[kk][tx * 8]);
            *(float4*)(rb + 4) = *(const float4*)(&Bs[kk][tx * 8 + 4]);
#pragma unroll
            for (int u = 0; u < 8; u++)
#pragma unroll
                for (int v = 0; v < 8; v++)
                    acc[u][v] = fmaf(ra[u], rb[v], acc[u][v]);
        }
        __syncthreads();
    }

#pragma unroll
    for (int u = 0; u < 8; u++) {
        int row = ty * 8 + u;
        size_t base = ((size_t)(b * NNODE + rt * 128 + row)) * CHID + tx * 8;
        __nv_bfloat16 hi8[8], lo8[8];
#pragma unroll
        for (int v = 0; v < 8; v++) {
            float val = acc[u][v];
            __nv_bfloat16 hi = __float2bfloat16(val);
            hi8[v] = hi;
            lo8[v] = __float2bfloat16(val - __bfloat162float(hi));
        }
        *(uint4*)(Hhi + base) = *(const uint4*)hi8;
        *(uint4*)(Hlo + base) = *(const uint4*)lo8;
    }
}

// ---------------- K4: mma.sync GCN GEMM (3-stage pipeline) ----------------
__device__ __forceinline__ void load_chunk(uint32_t st, int c, int tid,
                                           const char* Ah, const char* Al,
                                           const char* Bh, const char* Bl) {
#pragma unroll
    for (int i = 0; i < 2; i++) {
        int item = tid + i * 256;
        int row = item >> 2, seg = item & 3;
        uint32_t so = (uint32_t)(row * ASTR + seg * 16);
        size_t   go = (size_t)row * (NNODE * 2) + (size_t)c * (KC * 2) + seg * 16;
        cp16(st + OFF_AHI + so, Ah + go);
        cp16(st + OFF_ALO + so, Al + go);
    }
#pragma unroll
    for (int i = 0; i < 2; i++) {
        int item = tid + i * 256;
        int kr = item >> 4, seg = item & 15;
        uint32_t so = (uint32_t)(kr * HSTR + seg * 16);
        size_t   go = (size_t)(c * KC + kr) * (CHID * 2) + seg * 16;
        cp16(st + OFF_HHI + so, Bh + go);
        cp16(st + OFF_HLO + so, Bl + go);
    }
    CP_COMMIT();
}

template<bool POOL>
__global__ __launch_bounds__(256, 2)
void gcn_mma_kernel(const __nv_bfloat16* __restrict__ Ahi, const __nv_bfloat16* __restrict__ Alo,
                    const __nv_bfloat16* __restrict__ Hhi, const __nv_bfloat16* __restrict__ Hlo,
                    const float* __restrict__ bias, const int* __restrict__ mask,
                    float* __restrict__ Hout, float* __restrict__ part) {
    extern __shared__ char smem[];
    uint32_t sb = smem_u32(smem);
    int tid = threadIdx.x;
    int wid = tid >> 5, lane = tid & 31;
    int warpM = wid >> 2, warpN = wid & 3;

    int b = blockIdx.x >> 2, rt = blockIdx.x & 3;
    const char* Ah = (const char*)Ahi + ((size_t)(b * NNODE + rt * 128)) * (NNODE * 2);
    const char* Al = (const char*)Alo + ((size_t)(b * NNODE + rt * 128)) * (NNODE * 2);
    const char* Bh = (const char*)Hhi + ((size_t)b * NNODE) * (CHID * 2);
    const char* Bl = (const char*)Hlo + ((size_t)b * NNODE) * (CHID * 2);

    uint32_t aRow = (uint32_t)((warpM * 64 + (lane & 15)) * ASTR + (lane >> 4) * 16);
    uint32_t bRow = (uint32_t)(((lane & 7) + ((lane >> 3) & 1) * 8) * HSTR
                               + (warpN * 32 + ((lane >> 4) & 1) * 8) * 2);

    load_chunk(sb, 0, tid, Ah, Al, Bh, Bl);
    load_chunk(sb + STAGEB, 1, tid, Ah, Al, Bh, Bl);

    float acc[4][4][4];
#pragma unroll
    for (int m = 0; m < 4; m++)
#pragma unroll
        for (int n = 0; n < 4; n++)
#pragma unroll
            for (int k = 0; k < 4; k++) acc[m][n][k] = 0.f;

    int stg = 0;       // stage of chunk c
    for (int c = 0; c < NCHUNK; c++) {
        CP_WAIT1();            // chunk c landed (c+1 may still be in flight)
        __syncthreads();       // all warps past chunk c-1 compute; stage (c+2)%3 reusable
        int pstg = stg + 2; if (pstg >= NSTG) pstg -= NSTG;
        if (c + 2 < NCHUNK)
            load_chunk(sb + (uint32_t)pstg * STAGEB, c + 2, tid, Ah, Al, Bh, Bl);
        else
            CP_COMMIT();       // keep wait_group accounting constant
        uint32_t st = sb + (uint32_t)stg * STAGEB;
#pragma unroll
        for (int ks = 0; ks < KC / 16; ks++) {
            uint32_t ahi[4][4], alo[4][4];
#pragma unroll
            for (int mt = 0; mt < 4; mt++) {
                uint32_t ad = st + aRow + (uint32_t)(mt * 16 * ASTR + ks * 32);
                ldm_x4(ahi[mt][0], ahi[mt][1], ahi[mt][2], ahi[mt][3], ad + OFF_AHI);
                ldm_x4(alo[mt][0], alo[mt][1], alo[mt][2], alo[mt][3], ad + OFF_ALO);
            }
            uint32_t bhi[2][4], blo[2][4];
#pragma unroll
            for (int ng = 0; ng < 2; ng++) {
                uint32_t bd = st + bRow + (uint32_t)(ks * 16 * HSTR + ng * 32);
                ldm_x4t(bhi[ng][0], bhi[ng][1], bhi[ng][2], bhi[ng][3], bd + OFF_HHI);
                ldm_x4t(blo[ng][0], blo[ng][1], blo[ng][2], blo[ng][3], bd + OFF_HLO);
            }
#pragma unroll
            for (int mt = 0; mt < 4; mt++)
#pragma unroll
                for (int nt = 0; nt < 4; nt++) {
                    int ng = nt >> 1, hf = nt & 1;
                    mma16816(acc[mt][nt], ahi[mt], bhi[ng][hf * 2], bhi[ng][hf * 2 + 1]);
                    mma16816(acc[mt][nt], ahi[mt], blo[ng][hf * 2], blo[ng][hf * 2 + 1]);
                    mma16816(acc[mt][nt], alo[mt], bhi[ng][hf * 2], bhi[ng][hf * 2 + 1]);
                }
        }
        if (++stg >= NSTG) stg = 0;
    }

    // epilogue: bias + mask + silu
    int rowBase = b * NNODE + rt * 128 + warpM * 64;
    float* Ob = Hout + (size_t)rowBase * CHID;
    float csum[8];
#pragma unroll
    for (int k = 0; k < 8; k++) csum[k] = 0.f;

#pragma unroll
    for (int mt = 0; mt < 4; mt++) {
        int r0 = mt * 16 + (lane >> 2);
        float m0 = (float)mask[rowBase + r0];
        float m1 = (float)mask[rowBase + r0 + 8];
#pragma unroll
        for (int nt = 0; nt < 4; nt++) {
            int col = warpN * 32 + nt * 8 + (lane & 3) * 2;
            float b0v = bias[col], b1v = bias[col + 1];
            float z0 = (acc[mt][nt][0] + b0v) * m0;
            float z1 = (acc[mt][nt][1] + b1v) * m0;
            float z2 = (acc[mt][nt][2] + b0v) * m1;
            float z3 = (acc[mt][nt][3] + b1v) * m1;
            float o0 = z0 / (1.f + __expf(-z0));
            float o1 = z1 / (1.f + __expf(-z1));
            float o2 = z2 / (1.f + __expf(-z2));
            float o3 = z3 / (1.f + __expf(-z3));
            if (POOL) {
                csum[nt * 2]     += o0 + o2;
                csum[nt * 2 + 1] += o1 + o3;
            } else {
                *(float2*)(Ob + (size_t)r0 * CHID + col)       = make_float2(o0, o1);
                *(float2*)(Ob + (size_t)(r0 + 8) * CHID + col) = make_float2(o2, o3);
            }
        }
    }

    if (POOL) {
        __shared__ float spool[2][CHID];
#pragma unroll
        for (int off = 4; off < 32; off <<= 1)
#pragma unroll
            for (int k = 0; k < 8; k++)
                csum[k] += __shfl_xor_sync(0xffffffffu, csum[k], off);
        if ((lane >> 2) == 0) {
#pragma unroll
            for (int nt = 0; nt < 4; nt++) {
                int col = warpN * 32 + nt * 8 + (lane & 3) * 2;
                spool[warpM][col]     = csum[nt * 2];
                spool[warpM][col + 1] = csum[nt * 2 + 1];
            }
        }
        __syncthreads();
        if (tid < CHID)
            part[(b * 4 + rt) * CHID + tid] = spool[0][tid] + spool[1][tid];
    }
}

// ---------------- K5: head from pooled partials ----------------
__global__ void head_kernel(const float* __restrict__ part,
                            const float* __restrict__ Wl1, const float* __restrict__ bl1,
                            const float* __restrict__ Wl2, const float* __restrict__ bl2,
                            float* __restrict__ out) {
    int b = blockIdx.x;
    int c = threadIdx.x;     // 128 threads
    __shared__ float g[CHID], g1[CHID];
    const float* pb = part + b * 4 * CHID;
    g[c] = (pb[c] + pb[CHID + c] + pb[2 * CHID + c] + pb[3 * CHID + c]) * (1.0f / NNODE);
    __syncthreads();
    float acc = bl1[c];
    for (int k = 0; k < CHID; k++) acc = fmaf(g[k], Wl1[k * CHID + c], acc);
    g1[c] = acc / (1.f + __expf(-acc));
    __syncthreads();
    if (c < COUT) {
        float acc2 = bl2[c];
        for (int k = 0; k < CHID; k++) acc2 = fmaf(g1[k], Wl2[k * COUT + c], acc2);
        out[b * COUT + c] = acc2;
    }
}

// ---------------- launch ----------------
extern "C" void kernel_launch(void* const* d_in, const int* in_sizes, int n_in,
                              void* d_out, int out_size) {
    const float* x    = (const float*)d_in[0];
    const float* adj  = (const float*)d_in[1];
    const int*   mask = (const int*)  d_in[2];
    const float* W0   = (const float*)d_in[3];
    const float* b0   = (const float*)d_in[4];
    const float* W1   = (const float*)d_in[5];
    const float* b1   = (const float*)d_in[6];
    const float* Wl1  = (const float*)d_in[7];
    const float* bl1  = (const float*)d_in[8];
    const float* Wl2  = (const float*)d_in[9];
    const float* bl2  = (const float*)d_in[10];
    float* out = (float*)d_out;

    __nv_bfloat16 *dAhi, *dAlo, *dHhi, *dHlo;
    float *dHout, *dPart;
    cudaGetSymbolAddress((void**)&dAhi, g_Ahi);
    cudaGetSymbolAddress((void**)&dAlo, g_Alo);
    cudaGetSymbolAddress((void**)&dHhi, g_Hhi);
    cudaGetSymbolAddress((void**)&dHlo, g_Hlo);
    cudaGetSymbolAddress((void**)&dHout, g_hout);
    cudaGetSymbolAddress((void**)&dPart, g_part);

    static int smem_set = 0;
    if (!smem_set) {
        cudaFuncSetAttribute(gcn_mma_kernel<false>,
                             cudaFuncAttributeMaxDynamicSharedMemorySize, SMEM_DYN);
        cudaFuncSetAttribute(gcn_mma_kernel<true>,
                             cudaFuncAttributeMaxDynamicSharedMemorySize, SMEM_DYN);
        smem_set = 1;
    }

    // 1) degrees
    deg_kernel<<<BATCH * NNODE, 128>>>(adj);
    // 2) collapsed normalized adjacency (bf16 hi/lo)
    buildA_kernel<<<(BATCH * NNODE * NNODE) / (256 * 4), 256>>>(adj);
    // 3) H = x @ W0 (split bf16)
    lin_kernel<<<BATCH * 4, 256>>>(x, W0, CIN, dHhi, dHlo);
    // 4) layer 1 (writes h1 fp32)
    gcn_mma_kernel<false><<<BATCH * 4, 256, SMEM_DYN>>>(dAhi, dAlo, dHhi, dHlo, b0, mask,
                                                        dHout, dPart);
    // 5) H = h1 @ W1 (split bf16)
    lin_kernel<<<BATCH * 4, 256>>>(dHout, W1, CHID, dHhi, dHlo);
    // 6) layer 2 (fused mean-pool epilogue, no 16MB write)
    gcn_mma_kernel<true><<<BATCH * 4, 256, SMEM_DYN>>>(dAhi, dAlo, dHhi, dHlo, b1, mask,
                                                       dHout, dPart);
    // 7) MLP head from pooled partials
    head_kernel<<<BATCH, CHID>>>(dPart, Wl1, bl1, Wl2, bl2, out);
}